// round 6
// baseline (speedup 1.0000x reference)
#include <cuda_runtime.h>
#include <math.h>
#include <stdint.h>

#define NN 50000
#define EE 800000
#define DD 256
#define HH 4
#define CC 64
#define OUTC 5
#define FD (HH*OUTC)   // 20
#define NEG 0.2f
#define GN_EPS 1e-5f
#define SM_EPS 1e-16f

// ---------------- scratch (device globals, no allocation) ----------------
__device__ float g_emb[NN*DD];
__device__ float g_xl [NN*DD];
__device__ float g_xr [NN*DD];
__device__ float g_lin[NN*DD];
__device__ float g_agg[NN*DD];
__device__ float g_score[EE*HH];
__device__ float g_colstat[2*DD];
__device__ float g_mshift[DD];
__device__ float g_rsig  [DD];
__device__ float g_fxl [NN*FD];
__device__ float g_fxr [NN*FD];
__device__ float g_fagg[NN*FD];
__device__ float g_flin[NN*OUTC];
// CSR by destination
__device__ int g_deg[NN];
__device__ int g_off[NN+1];
__device__ int g_pos[NN];
__device__ int g_eperm[EE];

static __device__ __forceinline__ float tf32_rn(float x) {
    float r; asm("cvt.rna.tf32.f32 %0, %1;" : "=f"(r) : "f"(x)); return r;
}

#define MMA_TF32(c, a, b)                                                     \
    asm volatile("mma.sync.aligned.m16n8k8.row.col.f32.tf32.tf32.f32 "        \
                 "{%0,%1,%2,%3}, {%4,%5,%6,%7}, {%8,%9}, {%0,%1,%2,%3};"      \
                 : "+f"((c)[0]), "+f"((c)[1]), "+f"((c)[2]), "+f"((c)[3])     \
                 : "r"((a)[0]), "r"((a)[1]), "r"((a)[2]), "r"((a)[3]),        \
                   "r"((b)[0]), "r"((b)[1]))

// ---------------- tensor-core GEMM: C[M,256] = A[M,256] @ B[256,256] ------
// 3xTF32 (hi*hi + hi*lo + lo*hi). 128x128 CTA tile, 8 warps (2x4), 64x32
// per warp. K-chunks of 16, hi/lo smem, padded stride 132.
#define PADW 132
__global__ __launch_bounds__(256, 2)
void k_mma256(const float* __restrict__ A, const float* __restrict__ B,
              const float* __restrict__ bias, float* __restrict__ C, int M) {
    __shared__ float Ah[16][PADW], Al[16][PADW], Bh[16][PADW], Bl[16][PADW];

    const int tid = threadIdx.x;
    const int lane = tid & 31, wid = tid >> 5;
    const int warpRow = wid >> 2, warpCol = wid & 3;       // 2 x 4
    const int rowBase = blockIdx.y * 128;
    const int colBase = blockIdx.x * 128;

    float c[4][4][4];
    #pragma unroll
    for (int mt = 0; mt < 4; ++mt)
        #pragma unroll
        for (int nt = 0; nt < 4; ++nt)
            #pragma unroll
            for (int j = 0; j < 4; ++j) c[mt][nt][j] = 0.f;

    const int aRow = tid >> 1;                  // 0..127
    const int aQ   = (tid & 1) * 2;             // float4 quad base (0 or 2)
    const bool aOk = (rowBase + aRow) < M;

    const int mB = warpRow * 64 + (lane >> 2);
    const int nB = warpCol * 32 + (lane >> 2);
    const int kA = lane & 3;

    for (int ch = 0; ch < 16; ++ch) {
        // A chunk: 128 rows x 16 cols, transposed to [k][m] hi/lo
        #pragma unroll
        for (int i = 0; i < 2; ++i) {
            int q = aQ + i;
            float4 v = aOk ? *(const float4*)(A + (size_t)(rowBase + aRow) * 256
                                              + ch * 16 + q * 4)
                           : make_float4(0.f, 0.f, 0.f, 0.f);
            float hx = tf32_rn(v.x), hy = tf32_rn(v.y),
                  hz = tf32_rn(v.z), hw = tf32_rn(v.w);
            Ah[q*4+0][aRow] = hx;  Al[q*4+0][aRow] = tf32_rn(v.x - hx);
            Ah[q*4+1][aRow] = hy;  Al[q*4+1][aRow] = tf32_rn(v.y - hy);
            Ah[q*4+2][aRow] = hz;  Al[q*4+2][aRow] = tf32_rn(v.z - hz);
            Ah[q*4+3][aRow] = hw;  Al[q*4+3][aRow] = tf32_rn(v.w - hw);
        }
        // B chunk: 16 rows(k) x 128 cols(n), natural [k][n] hi/lo
        #pragma unroll
        for (int i = 0; i < 2; ++i) {
            int idx = tid + i * 256;
            int k = idx >> 5, q = idx & 31;
            float4 v = *(const float4*)(B + (size_t)(ch * 16 + k) * 256
                                        + colBase + q * 4);
            float hx = tf32_rn(v.x), hy = tf32_rn(v.y),
                  hz = tf32_rn(v.z), hw = tf32_rn(v.w);
            Bh[k][q*4+0] = hx;  Bl[k][q*4+0] = tf32_rn(v.x - hx);
            Bh[k][q*4+1] = hy;  Bl[k][q*4+1] = tf32_rn(v.y - hy);
            Bh[k][q*4+2] = hz;  Bl[k][q*4+2] = tf32_rn(v.z - hz);
            Bh[k][q*4+3] = hw;  Bl[k][q*4+3] = tf32_rn(v.w - hw);
        }
        __syncthreads();

        #pragma unroll
        for (int ks = 0; ks < 2; ++ks) {
            const int k0 = ks * 8;
            uint32_t af[4][4], bhf[4][2], blf[4][2];
            #pragma unroll
            for (int nt = 0; nt < 4; ++nt) {
                int n = nB + nt * 8;
                bhf[nt][0] = __float_as_uint(Bh[k0 + kA][n]);
                bhf[nt][1] = __float_as_uint(Bh[k0 + kA + 4][n]);
                blf[nt][0] = __float_as_uint(Bl[k0 + kA][n]);
                blf[nt][1] = __float_as_uint(Bl[k0 + kA + 4][n]);
            }
            #pragma unroll
            for (int mt = 0; mt < 4; ++mt) {
                int m = mB + mt * 16;
                af[mt][0] = __float_as_uint(Ah[k0 + kA][m]);
                af[mt][1] = __float_as_uint(Ah[k0 + kA][m + 8]);
                af[mt][2] = __float_as_uint(Ah[k0 + kA + 4][m]);
                af[mt][3] = __float_as_uint(Ah[k0 + kA + 4][m + 8]);
            }
            // hi*hi + hi*lo
            #pragma unroll
            for (int mt = 0; mt < 4; ++mt)
                #pragma unroll
                for (int nt = 0; nt < 4; ++nt) {
                    MMA_TF32(c[mt][nt], af[mt], bhf[nt]);
                    MMA_TF32(c[mt][nt], af[mt], blf[nt]);
                }
            // lo*hi (reuse af registers)
            #pragma unroll
            for (int mt = 0; mt < 4; ++mt) {
                int m = mB + mt * 16;
                af[mt][0] = __float_as_uint(Al[k0 + kA][m]);
                af[mt][1] = __float_as_uint(Al[k0 + kA][m + 8]);
                af[mt][2] = __float_as_uint(Al[k0 + kA + 4][m]);
                af[mt][3] = __float_as_uint(Al[k0 + kA + 4][m + 8]);
            }
            #pragma unroll
            for (int mt = 0; mt < 4; ++mt)
                #pragma unroll
                for (int nt = 0; nt < 4; ++nt)
                    MMA_TF32(c[mt][nt], af[mt], bhf[nt]);
        }
        __syncthreads();
    }

    // epilogue
    #pragma unroll
    for (int mt = 0; mt < 4; ++mt) {
        int row = rowBase + warpRow * 64 + mt * 16 + (lane >> 2);
        #pragma unroll
        for (int nt = 0; nt < 4; ++nt) {
            int col = colBase + warpCol * 32 + nt * 8 + (lane & 3) * 2;
            float b0 = bias ? bias[col] : 0.f;
            float b1 = bias ? bias[col + 1] : 0.f;
            if (row < M) {
                float2 o = make_float2(c[mt][nt][0] + b0, c[mt][nt][1] + b1);
                *(float2*)(C + (size_t)row * 256 + col) = o;
            }
            if (row + 8 < M) {
                float2 o = make_float2(c[mt][nt][2] + b0, c[mt][nt][3] + b1);
                *(float2*)(C + (size_t)(row + 8) * 256 + col) = o;
            }
        }
    }
}

// ---------------- scalar SGEMM (small-N final GEMMs) --------------
#define BM 128
#define BN 128
#define BK 8

static __device__ __forceinline__ float4 ldA4(const float* A, int M, int K,
                                              int row, int k) {
    if (row < M) return *(const float4*)(A + (size_t)row * K + k);
    return make_float4(0.f, 0.f, 0.f, 0.f);
}
static __device__ __forceinline__ float4 ldB4(const float* B, int Nc,
                                              int k, int col) {
    float4 v = make_float4(0.f, 0.f, 0.f, 0.f);
    const float* p = B + (size_t)k * Nc + col;
    if ((Nc & 3) == 0) {
        if (col + 3 < Nc) v = *(const float4*)p;
    } else {
        if (col + 0 < Nc) v.x = p[0];
        if (col + 1 < Nc) v.y = p[1];
        if (col + 2 < Nc) v.z = p[2];
        if (col + 3 < Nc) v.w = p[3];
    }
    return v;
}

__global__ __launch_bounds__(256, 2)
void k_sgemm(const float* __restrict__ A, const float* __restrict__ B,
             const float* __restrict__ bias, float* __restrict__ C,
             int M, int Nc, int K) {
    __shared__ float As[2][BK][BM];
    __shared__ float Bs[2][BK][BN];

    const int tid = threadIdx.x;
    const int tx = tid & 15;
    const int ty = tid >> 4;
    const int rowBase = blockIdx.y * BM;
    const int colBase = blockIdx.x * BN;

    const int aRow = tid >> 1;
    const int aCol = (tid & 1) * 4;
    const int bRow = tid >> 5;
    const int bCol = (tid & 31) * 4;

    float acc[8][8];
    #pragma unroll
    for (int i = 0; i < 8; ++i)
        #pragma unroll
        for (int j = 0; j < 8; ++j) acc[i][j] = 0.f;

    float4 ra = ldA4(A, M, K, rowBase + aRow, 0 + aCol);
    float4 rb = ldB4(B, Nc, 0 + bRow, colBase + bCol);
    As[0][aCol + 0][aRow] = ra.x;
    As[0][aCol + 1][aRow] = ra.y;
    As[0][aCol + 2][aRow] = ra.z;
    As[0][aCol + 3][aRow] = ra.w;
    *(float4*)&Bs[0][bRow][bCol] = rb;
    __syncthreads();

    const int nt = K / BK;
    for (int t = 0; t < nt; ++t) {
        const int cur = t & 1;
        if (t + 1 < nt) {
            ra = ldA4(A, M, K, rowBase + aRow, (t + 1) * BK + aCol);
            rb = ldB4(B, Nc, (t + 1) * BK + bRow, colBase + bCol);
        }
        #pragma unroll
        for (int k = 0; k < BK; ++k) {
            float4 a0 = *(const float4*)&As[cur][k][ty * 4];
            float4 a1 = *(const float4*)&As[cur][k][64 + ty * 4];
            float4 b0 = *(const float4*)&Bs[cur][k][tx * 4];
            float4 b1 = *(const float4*)&Bs[cur][k][64 + tx * 4];
            float av[8] = {a0.x, a0.y, a0.z, a0.w, a1.x, a1.y, a1.z, a1.w};
            float bv[8] = {b0.x, b0.y, b0.z, b0.w, b1.x, b1.y, b1.z, b1.w};
            #pragma unroll
            for (int i = 0; i < 8; ++i)
                #pragma unroll
                for (int j = 0; j < 8; ++j) acc[i][j] += av[i] * bv[j];
        }
        if (t + 1 < nt) {
            const int nb = cur ^ 1;
            As[nb][aCol + 0][aRow] = ra.x;
            As[nb][aCol + 1][aRow] = ra.y;
            As[nb][aCol + 2][aRow] = ra.z;
            As[nb][aCol + 3][aRow] = ra.w;
            *(float4*)&Bs[nb][bRow][bCol] = rb;
            __syncthreads();
        }
    }

    #pragma unroll
    for (int i = 0; i < 8; ++i) {
        int r = rowBase + (i < 4 ? ty * 4 + i : 64 + ty * 4 + (i - 4));
        if (r >= M) continue;
        #pragma unroll
        for (int j = 0; j < 8; ++j) {
            int c = colBase + (j < 4 ? tx * 4 + j : 64 + tx * 4 + (j - 4));
            if (c < Nc) {
                float v = acc[i][j];
                if (bias) v += bias[c];
                C[(size_t)r * Nc + c] = v;
            }
        }
    }
}

// ---------------- CSR build ----------------
__global__ void k_hist(const int* __restrict__ ei) {
    int e = blockIdx.x * blockDim.x + threadIdx.x;
    if (e < EE) atomicAdd(&g_deg[ei[EE + e]], 1);
}

__global__ void k_scan() {
    __shared__ int wsum[32];
    const int CH = 49;
    int t = threadIdx.x;
    int base = t * CH;
    int s = 0;
    for (int i = 0; i < CH; ++i) {
        int idx = base + i;
        if (idx < NN) s += g_deg[idx];
    }
    int lane = t & 31, wid = t >> 5;
    int v = s;
    #pragma unroll
    for (int d = 1; d < 32; d <<= 1) {
        int n = __shfl_up_sync(~0u, v, d);
        if (lane >= d) v += n;
    }
    if (lane == 31) wsum[wid] = v;
    __syncthreads();
    if (wid == 0) {
        int wv = wsum[lane];
        #pragma unroll
        for (int d = 1; d < 32; d <<= 1) {
            int n = __shfl_up_sync(~0u, wv, d);
            if (lane >= d) wv += n;
        }
        wsum[lane] = wv;
    }
    __syncthreads();
    int pre = (v - s) + (wid > 0 ? wsum[wid - 1] : 0);
    for (int i = 0; i < CH; ++i) {
        int idx = base + i;
        if (idx < NN) { g_off[idx] = pre; pre += g_deg[idx]; }
    }
    if (t == 1023) g_off[NN] = pre;
}

__global__ void k_scatter(const int* __restrict__ ei) {
    int e = blockIdx.x * blockDim.x + threadIdx.x;
    if (e >= EE) return;
    int dst = ei[EE + e];
    int p = atomicAdd(&g_pos[dst], 1);
    g_eperm[g_off[dst] + p] = e;
}

// ---------------- edge scoring ----------------
__global__ void k_edge_score64(const float4* __restrict__ xl,
                               const float4* __restrict__ xr,
                               const float* __restrict__ att,
                               const int* __restrict__ ei) {
    __shared__ float4 satt[64];
    int tid = threadIdx.x;
    if (tid < 64) satt[tid] = ((const float4*)att)[tid];
    __syncthreads();
    int idx = blockIdx.x * 256 + tid;
    if (idx >= EE * HH) return;
    int e = idx >> 2, h = idx & 3;
    int src = ei[e], dst = ei[EE + e];
    const float4* pl = xl + (size_t)src * 64 + h * 16;
    const float4* pr = xr + (size_t)dst * 64 + h * 16;
    float s = 0.f;
    #pragma unroll
    for (int g = 0; g < 16; ++g) {
        float4 a = pl[g], b = pr[g], w = satt[h * 16 + g];
        float v;
        v = a.x + b.x; v = v > 0.f ? v : NEG * v; s += w.x * v;
        v = a.y + b.y; v = v > 0.f ? v : NEG * v; s += w.y * v;
        v = a.z + b.z; v = v > 0.f ? v : NEG * v; s += w.z * v;
        v = a.w + b.w; v = v > 0.f ? v : NEG * v; s += w.w * v;
    }
    g_score[idx] = s;
}

__global__ void k_edge_score_f(const float* __restrict__ xl,
                               const float* __restrict__ xr,
                               const float* __restrict__ att,
                               const int* __restrict__ ei) {
    int idx = blockIdx.x * blockDim.x + threadIdx.x;
    if (idx >= EE * HH) return;
    int e = idx >> 2, h = idx & 3;
    int src = ei[e], dst = ei[EE + e];
    const float* pl = xl + (size_t)src * FD + h * OUTC;
    const float* pr = xr + (size_t)dst * FD + h * OUTC;
    const float* pa = att + h * OUTC;
    float s = 0.f;
    #pragma unroll
    for (int c = 0; c < OUTC; ++c) {
        float v = pl[c] + pr[c];
        v = v > 0.f ? v : NEG * v;
        s += pa[c] * v;
    }
    g_score[idx] = s;
}

// ---------------- segment softmax ----------------
__global__ void k_softmax_csr() {
    int w = (blockIdx.x * blockDim.x + threadIdx.x) >> 5;
    if (w >= NN) return;
    int lane = threadIdx.x & 31;
    int beg = g_off[w], end = g_off[w + 1];
    int h = lane & 3;
    int j0 = beg + (lane >> 2);

    float m = -1e30f;
    for (int j = j0; j < end; j += 8) {
        int e = g_eperm[j];
        m = fmaxf(m, g_score[e * 4 + h]);
    }
    #pragma unroll
    for (int d = 4; d < 32; d <<= 1) m = fmaxf(m, __shfl_xor_sync(~0u, m, d));

    float den = 0.f;
    for (int j = j0; j < end; j += 8) {
        int e = g_eperm[j];
        den += expf(g_score[e * 4 + h] - m);
    }
    #pragma unroll
    for (int d = 4; d < 32; d <<= 1) den += __shfl_xor_sync(~0u, den, d);
    float inv = 1.f / (den + SM_EPS);

    for (int j = j0; j < end; j += 8) {
        int e = g_eperm[j];
        g_score[e * 4 + h] = expf(g_score[e * 4 + h] - m) * inv;
    }
}

// ---------------- aggregation ----------------
__global__ void k_agg_csr(const int* __restrict__ ei,
                          const float4* __restrict__ xl) {
    int node = blockIdx.x * 4 + (threadIdx.x >> 6);
    int t = threadIdx.x & 63;
    int h = t >> 4;
    int beg = g_off[node], end = g_off[node + 1];
    float4 acc = make_float4(0.f, 0.f, 0.f, 0.f);
    for (int j = beg; j < end; ++j) {
        int e = g_eperm[j];
        int src = ei[e];
        float a = g_score[e * 4 + h];
        float4 v = xl[(size_t)src * 64 + t];
        acc.x += a * v.x; acc.y += a * v.y; acc.z += a * v.z; acc.w += a * v.w;
    }
    ((float4*)g_agg)[(size_t)node * 64 + t] = acc;
}

__global__ void k_agg_csr_f(const int* __restrict__ ei) {
    int node = blockIdx.x * 8 + (threadIdx.x >> 5);
    int t = threadIdx.x & 31;
    if (t >= FD) return;
    int h = t / OUTC;
    int beg = g_off[node], end = g_off[node + 1];
    float acc = 0.f;
    for (int j = beg; j < end; ++j) {
        int e = g_eperm[j];
        int src = ei[e];
        acc += g_score[e * 4 + h] * g_fxl[(size_t)src * FD + t];
    }
    g_fagg[(size_t)node * FD + t] = acc;
}

// ---------------- GraphNorm ----------------
__global__ void k_colstats(const float* __restrict__ bconv) {
    int t = threadIdx.x;
    float bc = bconv[t];
    float s = 0.f, q = 0.f;
    for (int r = blockIdx.x; r < NN; r += gridDim.x) {
        float v = g_agg[(size_t)r * DD + t] + bc;
        s += v; q += v * v;
    }
    atomicAdd(&g_colstat[t], s);
    atomicAdd(&g_colstat[DD + t], q);
}

__global__ void k_finstats(const float* __restrict__ gnw, const float* __restrict__ gnms) {
    int t = threadIdx.x;
    float mean = g_colstat[t] * (1.f / NN);
    float ms = mean * gnms[t];
    float var = g_colstat[DD + t] * (1.f / NN) - 2.f * ms * mean + ms * ms;
    g_mshift[t] = ms;
    g_rsig[t] = gnw[t] * rsqrtf(var + GN_EPS);
}

__global__ void k_fuse(const float* __restrict__ bconv, const float* __restrict__ gnb) {
    int i = blockIdx.x * blockDim.x + threadIdx.x;
    if (i >= NN * (DD / 4)) return;
    int c4 = (i & 63) * 4;
    float4 v = ((const float4*)g_agg)[i];
    float4 l = ((const float4*)g_lin)[i];
    float4 r;
    float t;
    t = (v.x + bconv[c4+0] - g_mshift[c4+0]) * g_rsig[c4+0] + gnb[c4+0] + l.x;
    r.x = t > 0.f ? t : expm1f(t);
    t = (v.y + bconv[c4+1] - g_mshift[c4+1]) * g_rsig[c4+1] + gnb[c4+1] + l.y;
    r.y = t > 0.f ? t : expm1f(t);
    t = (v.z + bconv[c4+2] - g_mshift[c4+2]) * g_rsig[c4+2] + gnb[c4+2] + l.z;
    r.z = t > 0.f ? t : expm1f(t);
    t = (v.w + bconv[c4+3] - g_mshift[c4+3]) * g_rsig[c4+3] + gnb[c4+3] + l.w;
    r.w = t > 0.f ? t : expm1f(t);
    ((float4*)g_emb)[i] = r;
}

// ---------------- final combine + log_softmax ----------------
__global__ void k_final(const float* __restrict__ fbconv, float* __restrict__ out) {
    int n = blockIdx.x * blockDim.x + threadIdx.x;
    if (n >= NN) return;
    float t[OUTC];
    #pragma unroll
    for (int o = 0; o < OUTC; ++o) {
        float s = 0.f;
        #pragma unroll
        for (int h = 0; h < HH; ++h) s += g_fagg[(size_t)n * FD + h * OUTC + o];
        t[o] = 0.25f * s + fbconv[o] + g_flin[(size_t)n * OUTC + o];
    }
    float m = t[0];
    #pragma unroll
    for (int o = 1; o < OUTC; ++o) m = fmaxf(m, t[o]);
    float lse = 0.f;
    #pragma unroll
    for (int o = 0; o < OUTC; ++o) lse += expf(t[o] - m);
    lse = logf(lse);
    #pragma unroll
    for (int o = 0; o < OUTC; ++o) out[(size_t)n * OUTC + o] = t[o] - m - lse;
}

// ---------------- host ----------------
static void tgemm(const float* A, const float* B, const float* bias, float* C, int M) {
    dim3 grid(2, (M + 127) / 128);
    k_mma256<<<grid, 256>>>(A, B, bias, C, M);
}
static void sgemm(const float* A, const float* B, const float* bias, float* C,
                  int M, int Nc, int K) {
    dim3 grid((Nc + BN - 1) / BN, (M + BM - 1) / BM);
    k_sgemm<<<grid, 256>>>(A, B, bias, C, M, Nc, K);
}

extern "C" void kernel_launch(void* const* d_in, const int* in_sizes, int n_in,
                              void* d_out, int out_size) {
    const float* x      = (const float*)d_in[0];
    const int*   ei     = (const int*)d_in[1];
    const float* Wl     = (const float*)d_in[2];
    const float* Wr     = (const float*)d_in[3];
    const float* att    = (const float*)d_in[4];
    const float* bconv  = (const float*)d_in[5];
    const float* Wlin   = (const float*)d_in[6];
    const float* blin   = (const float*)d_in[7];
    const float* gnw    = (const float*)d_in[8];
    const float* gnb    = (const float*)d_in[9];
    const float* gnms   = (const float*)d_in[10];
    const float* fWl    = (const float*)d_in[11];
    const float* fWr    = (const float*)d_in[12];
    const float* fatt   = (const float*)d_in[13];
    const float* fbconv = (const float*)d_in[14];
    const float* fWlin  = (const float*)d_in[15];
    const float* fblin  = (const float*)d_in[16];
    float* out = (float*)d_out;

    float *p_emb, *p_xl, *p_xr, *p_lin, *p_fxl, *p_fxr, *p_flin, *p_colstat;
    int *p_deg, *p_pos;
    cudaGetSymbolAddress((void**)&p_emb,  g_emb);
    cudaGetSymbolAddress((void**)&p_xl,   g_xl);
    cudaGetSymbolAddress((void**)&p_xr,   g_xr);
    cudaGetSymbolAddress((void**)&p_lin,  g_lin);
    cudaGetSymbolAddress((void**)&p_fxl,  g_fxl);
    cudaGetSymbolAddress((void**)&p_fxr,  g_fxr);
    cudaGetSymbolAddress((void**)&p_flin, g_flin);
    cudaGetSymbolAddress((void**)&p_colstat, g_colstat);
    cudaGetSymbolAddress((void**)&p_deg,  g_deg);
    cudaGetSymbolAddress((void**)&p_pos,  g_pos);

    const int EH_BLOCKS = (EE * HH + 255) / 256;
    const int E_BLOCKS  = (EE + 255) / 256;

    // ---- CSR build ----
    cudaMemsetAsync(p_deg, 0, NN * sizeof(int));
    cudaMemsetAsync(p_pos, 0, NN * sizeof(int));
    k_hist<<<E_BLOCKS, 256>>>(ei);
    k_scan<<<1, 1024>>>();
    k_scatter<<<E_BLOCKS, 256>>>(ei);

    const float* embp = x;
    for (int i = 0; i < 2; ++i) {
        const size_t wo = (size_t)i * DD * DD;
        tgemm(embp, Wl + wo, nullptr, p_xl, NN);
        tgemm(embp, Wr + wo, nullptr, p_xr, NN);
        tgemm(embp, Wlin + wo, blin + i * DD, p_lin, NN);
        k_edge_score64<<<EH_BLOCKS, 256>>>((const float4*)p_xl, (const float4*)p_xr,
                                           att + i * HH * CC, ei);
        k_softmax_csr<<<(NN + 7) / 8, 256>>>();
        k_agg_csr<<<NN / 4, 256>>>(ei, (const float4*)p_xl);
        cudaMemsetAsync(p_colstat, 0, 2 * DD * sizeof(float));
        k_colstats<<<256, 256>>>(bconv + i * DD);
        k_finstats<<<1, 256>>>(gnw + i * DD, gnms + i * DD);
        k_fuse<<<(NN * (DD / 4) + 255) / 256, 256>>>(bconv + i * DD, gnb + i * DD);
        embp = p_emb;
    }

    // final layer
    sgemm(p_emb, fWl, nullptr, p_fxl, NN, FD, DD);
    sgemm(p_emb, fWr, nullptr, p_fxr, NN, FD, DD);
    sgemm(p_emb, fWlin, fblin, p_flin, NN, OUTC, DD);
    k_edge_score_f<<<EH_BLOCKS, 256>>>(p_fxl, p_fxr, fatt, ei);
    k_softmax_csr<<<(NN + 7) / 8, 256>>>();
    k_agg_csr_f<<<NN / 8, 256>>>(ei);
    k_final<<<(NN + 255) / 256, 256>>>(fbconv, out);
}

// round 7
// speedup vs baseline: 1.3574x; 1.3574x over previous
#include <cuda_runtime.h>
#include <math.h>
#include <stdint.h>

#define NN 50000
#define EE 800000
#define DD 256
#define HH 4
#define CC 64
#define OUTC 5
#define FD (HH*OUTC)   // 20
#define NEG 0.2f
#define GN_EPS 1e-5f
#define SM_EPS 1e-16f

// ---------------- scratch (device globals, no allocation) ----------------
__device__ float g_emb[NN*DD];
__device__ float g_xl [NN*DD];
__device__ float g_xr [NN*DD];
__device__ float g_lin[NN*DD];
__device__ float g_agg[NN*DD];
__device__ float g_score[EE*HH];
__device__ float g_colstat[2*DD];
__device__ float g_mshift[DD];
__device__ float g_rsig  [DD];
__device__ float g_fxl [NN*FD];
__device__ float g_fxr [NN*FD];
__device__ float g_fagg[NN*FD];
__device__ float g_flin[NN*OUTC];
// CSR by destination
__device__ int g_deg[NN];
__device__ int g_off[NN+1];
__device__ int g_pos[NN];
__device__ int g_esrc[EE];
__device__ int g_edst[EE];

static __device__ __forceinline__ float tf32_rn(float x) {
    float r; asm("cvt.rna.tf32.f32 %0, %1;" : "=f"(r) : "f"(x)); return r;
}

#define MMA_TF32(c, a, b)                                                     \
    asm volatile("mma.sync.aligned.m16n8k8.row.col.f32.tf32.tf32.f32 "        \
                 "{%0,%1,%2,%3}, {%4,%5,%6,%7}, {%8,%9}, {%0,%1,%2,%3};"      \
                 : "+f"((c)[0]), "+f"((c)[1]), "+f"((c)[2]), "+f"((c)[3])     \
                 : "r"((a)[0]), "r"((a)[1]), "r"((a)[2]), "r"((a)[3]),        \
                   "r"((b)[0]), "r"((b)[1]))

// ---------------- tensor-core GEMM: 3 outputs in one launch ---------------
// C{0,1,2}[M,256] = A[M,256] @ B{0,1,2}[256,256]. 3xTF32 compensation.
// 128x128 CTA tile, 8 warps (2x4), 64x32 per warp. A raw smem (reg split),
// B hi/lo smem. Stride 136 (== 8 mod 32) -> conflict-free fragment loads.
#define PADW 136
__global__ __launch_bounds__(256, 2)
void k_mma3(const float* __restrict__ A,
            const float* __restrict__ B0, const float* __restrict__ B1,
            const float* __restrict__ B2, const float* __restrict__ bias2,
            float* __restrict__ C0, float* __restrict__ C1,
            float* __restrict__ C2, int M) {
    __shared__ float As[16][PADW];
    __shared__ float Bh[16][PADW], Bl[16][PADW];

    const int mat = blockIdx.x >> 1;
    const float* __restrict__ B = (mat == 0) ? B0 : (mat == 1) ? B1 : B2;
    float* __restrict__ C = (mat == 0) ? C0 : (mat == 1) ? C1 : C2;
    const float* bias = (mat == 2) ? bias2 : nullptr;

    const int tid = threadIdx.x;
    const int lane = tid & 31, wid = tid >> 5;
    const int warpRow = wid >> 2, warpCol = wid & 3;       // 2 x 4
    const int rowBase = blockIdx.y * 128;
    const int colBase = (blockIdx.x & 1) * 128;

    float c[4][4][4];
    #pragma unroll
    for (int mt = 0; mt < 4; ++mt)
        #pragma unroll
        for (int nt = 0; nt < 4; ++nt)
            #pragma unroll
            for (int j = 0; j < 4; ++j) c[mt][nt][j] = 0.f;

    const int aRow = tid >> 1;
    const int aQ   = (tid & 1) * 2;
    const bool aOk = (rowBase + aRow) < M;
    const int kB = tid >> 5, qB = tid & 31;

    const int mB = warpRow * 64 + (lane >> 2);
    const int nB = warpCol * 32 + (lane >> 2);
    const int kA = lane & 3;

    for (int ch = 0; ch < 16; ++ch) {
        // A chunk raw, transposed [k][m]
        #pragma unroll
        for (int i = 0; i < 2; ++i) {
            int q = aQ + i;
            float4 v = aOk ? *(const float4*)(A + (size_t)(rowBase + aRow) * 256
                                              + ch * 16 + q * 4)
                           : make_float4(0.f, 0.f, 0.f, 0.f);
            As[q*4+0][aRow] = v.x;
            As[q*4+1][aRow] = v.y;
            As[q*4+2][aRow] = v.z;
            As[q*4+3][aRow] = v.w;
        }
        // B chunk hi/lo, natural [k][n], float4 stores
        #pragma unroll
        for (int i = 0; i < 2; ++i) {
            int k = kB + i * 8;
            float4 v = *(const float4*)(B + (size_t)(ch * 16 + k) * 256
                                        + colBase + qB * 4);
            float4 h, l;
            h.x = tf32_rn(v.x); l.x = tf32_rn(v.x - h.x);
            h.y = tf32_rn(v.y); l.y = tf32_rn(v.y - h.y);
            h.z = tf32_rn(v.z); l.z = tf32_rn(v.z - h.z);
            h.w = tf32_rn(v.w); l.w = tf32_rn(v.w - h.w);
            *(float4*)&Bh[k][qB * 4] = h;
            *(float4*)&Bl[k][qB * 4] = l;
        }
        __syncthreads();

        #pragma unroll
        for (int ks = 0; ks < 2; ++ks) {
            const int k0 = ks * 8;
            uint32_t bhf[4][2], blf[4][2];
            #pragma unroll
            for (int nt = 0; nt < 4; ++nt) {
                int n = nB + nt * 8;
                bhf[nt][0] = __float_as_uint(Bh[k0 + kA][n]);
                bhf[nt][1] = __float_as_uint(Bh[k0 + kA + 4][n]);
                blf[nt][0] = __float_as_uint(Bl[k0 + kA][n]);
                blf[nt][1] = __float_as_uint(Bl[k0 + kA + 4][n]);
            }
            #pragma unroll
            for (int mt = 0; mt < 4; ++mt) {
                int m = mB + mt * 16;
                float r0 = As[k0 + kA][m];
                float r1 = As[k0 + kA][m + 8];
                float r2 = As[k0 + kA + 4][m];
                float r3 = As[k0 + kA + 4][m + 8];
                float h0 = tf32_rn(r0), h1 = tf32_rn(r1),
                      h2 = tf32_rn(r2), h3 = tf32_rn(r3);
                uint32_t ahi[4] = {__float_as_uint(h0), __float_as_uint(h1),
                                   __float_as_uint(h2), __float_as_uint(h3)};
                uint32_t alo[4] = {__float_as_uint(tf32_rn(r0 - h0)),
                                   __float_as_uint(tf32_rn(r1 - h1)),
                                   __float_as_uint(tf32_rn(r2 - h2)),
                                   __float_as_uint(tf32_rn(r3 - h3))};
                #pragma unroll
                for (int nt = 0; nt < 4; ++nt) {
                    MMA_TF32(c[mt][nt], ahi, bhf[nt]);
                    MMA_TF32(c[mt][nt], ahi, blf[nt]);
                    MMA_TF32(c[mt][nt], alo, bhf[nt]);
                }
            }
        }
        __syncthreads();
    }

    // epilogue
    #pragma unroll
    for (int mt = 0; mt < 4; ++mt) {
        int row = rowBase + warpRow * 64 + mt * 16 + (lane >> 2);
        #pragma unroll
        for (int nt = 0; nt < 4; ++nt) {
            int col = colBase + warpCol * 32 + nt * 8 + (lane & 3) * 2;
            float b0 = bias ? bias[col] : 0.f;
            float b1 = bias ? bias[col + 1] : 0.f;
            if (row < M) {
                float2 o = make_float2(c[mt][nt][0] + b0, c[mt][nt][1] + b1);
                *(float2*)(C + (size_t)row * 256 + col) = o;
            }
            if (row + 8 < M) {
                float2 o = make_float2(c[mt][nt][2] + b0, c[mt][nt][3] + b1);
                *(float2*)(C + (size_t)(row + 8) * 256 + col) = o;
            }
        }
    }
}

// ---------------- small-N GEMM: C[M,Nc] = A[M,256] @ B[256,Nc], Nc<=32 ----
__global__ __launch_bounds__(256)
void k_gemm_small(const float* __restrict__ A, const float* __restrict__ B,
                  const float* __restrict__ bias, float* __restrict__ C,
                  int M, int Nc) {
    __shared__ float As[16][129];
    __shared__ float Bs[16][32];
    const int tid = threadIdx.x;
    const int tx = tid & 31, ty = tid >> 5;
    const int rowBase = blockIdx.x * 128;
    const int aRow = tid >> 1, aQ = (tid & 1) * 2;
    const bool aOk = (rowBase + aRow) < M;

    float acc[16];
    #pragma unroll
    for (int r = 0; r < 16; ++r) acc[r] = 0.f;

    for (int ch = 0; ch < 16; ++ch) {
        #pragma unroll
        for (int i = 0; i < 2; ++i) {
            int q = aQ + i;
            float4 v = aOk ? *(const float4*)(A + (size_t)(rowBase + aRow) * 256
                                              + ch * 16 + q * 4)
                           : make_float4(0.f, 0.f, 0.f, 0.f);
            As[q*4+0][aRow] = v.x;
            As[q*4+1][aRow] = v.y;
            As[q*4+2][aRow] = v.z;
            As[q*4+3][aRow] = v.w;
        }
        #pragma unroll
        for (int i = 0; i < 2; ++i) {
            int idx = tid + i * 256;
            int k = idx >> 5, cc = idx & 31;
            Bs[k][cc] = (cc < Nc) ? B[(size_t)(ch * 16 + k) * Nc + cc] : 0.f;
        }
        __syncthreads();
        #pragma unroll
        for (int k = 0; k < 16; ++k) {
            float b = Bs[k][tx];
            #pragma unroll
            for (int r = 0; r < 16; ++r) acc[r] += As[k][ty * 16 + r] * b;
        }
        __syncthreads();
    }
    if (tx < Nc) {
        float bb = bias ? bias[tx] : 0.f;
        #pragma unroll
        for (int r = 0; r < 16; ++r) {
            int row = rowBase + ty * 16 + r;
            if (row < M) C[(size_t)row * Nc + tx] = acc[r] + bb;
        }
    }
}

// ---------------- CSR build ----------------
__global__ void k_hist(const int* __restrict__ ei) {
    int e = blockIdx.x * blockDim.x + threadIdx.x;
    if (e < EE) atomicAdd(&g_deg[ei[EE + e]], 1);
}

__global__ void k_scan() {
    __shared__ int wsum[32];
    const int CH = 49;
    int t = threadIdx.x;
    int base = t * CH;
    int s = 0;
    for (int i = 0; i < CH; ++i) {
        int idx = base + i;
        if (idx < NN) s += g_deg[idx];
    }
    int lane = t & 31, wid = t >> 5;
    int v = s;
    #pragma unroll
    for (int d = 1; d < 32; d <<= 1) {
        int n = __shfl_up_sync(~0u, v, d);
        if (lane >= d) v += n;
    }
    if (lane == 31) wsum[wid] = v;
    __syncthreads();
    if (wid == 0) {
        int wv = wsum[lane];
        #pragma unroll
        for (int d = 1; d < 32; d <<= 1) {
            int n = __shfl_up_sync(~0u, wv, d);
            if (lane >= d) wv += n;
        }
        wsum[lane] = wv;
    }
    __syncthreads();
    int pre = (v - s) + (wid > 0 ? wsum[wid - 1] : 0);
    for (int i = 0; i < CH; ++i) {
        int idx = base + i;
        if (idx < NN) { g_off[idx] = pre; pre += g_deg[idx]; }
    }
    if (t == 1023) g_off[NN] = pre;
}

__global__ void k_scatter(const int* __restrict__ ei) {
    int e = blockIdx.x * blockDim.x + threadIdx.x;
    if (e >= EE) return;
    int src = ei[e], dst = ei[EE + e];
    int p = atomicAdd(&g_pos[dst], 1);
    int slot = g_off[dst] + p;
    g_esrc[slot] = src;
    g_edst[slot] = dst;
}

// ---------------- edge scoring (CSR slot order, coalesced) ----------------
__global__ void k_edge_score64(const float4* __restrict__ xl,
                               const float4* __restrict__ xr,
                               const float* __restrict__ att) {
    __shared__ float4 satt[64];
    int tid = threadIdx.x;
    if (tid < 64) satt[tid] = ((const float4*)att)[tid];
    __syncthreads();
    int idx = blockIdx.x * 256 + tid;
    if (idx >= EE * HH) return;
    int j = idx >> 2, h = idx & 3;
    int src = g_esrc[j], dst = g_edst[j];
    const float4* pl = xl + (size_t)src * 64 + h * 16;
    const float4* pr = xr + (size_t)dst * 64 + h * 16;
    float s = 0.f;
    #pragma unroll
    for (int g = 0; g < 16; ++g) {
        float4 a = pl[g], b = pr[g], w = satt[h * 16 + g];
        float v;
        v = a.x + b.x; v = v > 0.f ? v : NEG * v; s += w.x * v;
        v = a.y + b.y; v = v > 0.f ? v : NEG * v; s += w.y * v;
        v = a.z + b.z; v = v > 0.f ? v : NEG * v; s += w.z * v;
        v = a.w + b.w; v = v > 0.f ? v : NEG * v; s += w.w * v;
    }
    g_score[idx] = s;
}

__global__ void k_edge_score_f(const float* __restrict__ xl,
                               const float* __restrict__ xr,
                               const float* __restrict__ att) {
    int idx = blockIdx.x * blockDim.x + threadIdx.x;
    if (idx >= EE * HH) return;
    int j = idx >> 2, h = idx & 3;
    int src = g_esrc[j], dst = g_edst[j];
    const float* pl = xl + (size_t)src * FD + h * OUTC;
    const float* pr = xr + (size_t)dst * FD + h * OUTC;
    const float* pa = att + h * OUTC;
    float s = 0.f;
    #pragma unroll
    for (int c = 0; c < OUTC; ++c) {
        float v = pl[c] + pr[c];
        v = v > 0.f ? v : NEG * v;
        s += pa[c] * v;
    }
    g_score[idx] = s;
}

// ---------------- segment softmax (contiguous, coalesced) ----------------
__global__ void k_softmax_csr() {
    int w = (blockIdx.x * blockDim.x + threadIdx.x) >> 5;
    if (w >= NN) return;
    int lane = threadIdx.x & 31;
    int beg = g_off[w], end = g_off[w + 1];
    int h = lane & 3;
    int j0 = beg + (lane >> 2);

    float m = -1e30f;
    for (int j = j0; j < end; j += 8) m = fmaxf(m, g_score[j * 4 + h]);
    #pragma unroll
    for (int d = 4; d < 32; d <<= 1) m = fmaxf(m, __shfl_xor_sync(~0u, m, d));

    float den = 0.f;
    for (int j = j0; j < end; j += 8) den += __expf(g_score[j * 4 + h] - m);
    #pragma unroll
    for (int d = 4; d < 32; d <<= 1) den += __shfl_xor_sync(~0u, den, d);
    float inv = 1.f / (den + SM_EPS);

    for (int j = j0; j < end; j += 8)
        g_score[j * 4 + h] = __expf(g_score[j * 4 + h] - m) * inv;
}

// ---------------- aggregation (gather) ----------------
__global__ void k_agg_csr(const float4* __restrict__ xl) {
    int node = blockIdx.x * 4 + (threadIdx.x >> 6);
    int t = threadIdx.x & 63;
    int h = t >> 4;
    int beg = g_off[node], end = g_off[node + 1];
    float4 acc = make_float4(0.f, 0.f, 0.f, 0.f);
    for (int j = beg; j < end; ++j) {
        int src = g_esrc[j];
        float a = g_score[j * 4 + h];
        float4 v = xl[(size_t)src * 64 + t];
        acc.x += a * v.x; acc.y += a * v.y; acc.z += a * v.z; acc.w += a * v.w;
    }
    ((float4*)g_agg)[(size_t)node * 64 + t] = acc;
}

__global__ void k_agg_csr_f() {
    int node = blockIdx.x * 8 + (threadIdx.x >> 5);
    int t = threadIdx.x & 31;
    if (t >= FD) return;
    int h = t / OUTC;
    int beg = g_off[node], end = g_off[node + 1];
    float acc = 0.f;
    for (int j = beg; j < end; ++j) {
        int src = g_esrc[j];
        acc += g_score[j * 4 + h] * g_fxl[(size_t)src * FD + t];
    }
    g_fagg[(size_t)node * FD + t] = acc;
}

// ---------------- GraphNorm ----------------
__global__ void k_colstats(const float* __restrict__ bconv) {
    int t = threadIdx.x;
    float bc = bconv[t];
    float s = 0.f, q = 0.f;
    for (int r = blockIdx.x; r < NN; r += gridDim.x) {
        float v = g_agg[(size_t)r * DD + t] + bc;
        s += v; q += v * v;
    }
    atomicAdd(&g_colstat[t], s);
    atomicAdd(&g_colstat[DD + t], q);
}

__global__ void k_finstats(const float* __restrict__ gnw, const float* __restrict__ gnms) {
    int t = threadIdx.x;
    float mean = g_colstat[t] * (1.f / NN);
    float ms = mean * gnms[t];
    float var = g_colstat[DD + t] * (1.f / NN) - 2.f * ms * mean + ms * ms;
    g_mshift[t] = ms;
    g_rsig[t] = gnw[t] * rsqrtf(var + GN_EPS);
}

__global__ void k_fuse(const float* __restrict__ bconv, const float* __restrict__ gnb) {
    int i = blockIdx.x * blockDim.x + threadIdx.x;
    if (i >= NN * (DD / 4)) return;
    int c4 = (i & 63) * 4;
    float4 v = ((const float4*)g_agg)[i];
    float4 l = ((const float4*)g_lin)[i];
    float4 r;
    float t;
    t = (v.x + bconv[c4+0] - g_mshift[c4+0]) * g_rsig[c4+0] + gnb[c4+0] + l.x;
    r.x = t > 0.f ? t : expm1f(t);
    t = (v.y + bconv[c4+1] - g_mshift[c4+1]) * g_rsig[c4+1] + gnb[c4+1] + l.y;
    r.y = t > 0.f ? t : expm1f(t);
    t = (v.z + bconv[c4+2] - g_mshift[c4+2]) * g_rsig[c4+2] + gnb[c4+2] + l.z;
    r.z = t > 0.f ? t : expm1f(t);
    t = (v.w + bconv[c4+3] - g_mshift[c4+3]) * g_rsig[c4+3] + gnb[c4+3] + l.w;
    r.w = t > 0.f ? t : expm1f(t);
    ((float4*)g_emb)[i] = r;
}

// ---------------- final combine + log_softmax ----------------
__global__ void k_final(const float* __restrict__ fbconv, float* __restrict__ out) {
    int n = blockIdx.x * blockDim.x + threadIdx.x;
    if (n >= NN) return;
    float t[OUTC];
    #pragma unroll
    for (int o = 0; o < OUTC; ++o) {
        float s = 0.f;
        #pragma unroll
        for (int h = 0; h < HH; ++h) s += g_fagg[(size_t)n * FD + h * OUTC + o];
        t[o] = 0.25f * s + fbconv[o] + g_flin[(size_t)n * OUTC + o];
    }
    float m = t[0];
    #pragma unroll
    for (int o = 1; o < OUTC; ++o) m = fmaxf(m, t[o]);
    float lse = 0.f;
    #pragma unroll
    for (int o = 0; o < OUTC; ++o) lse += expf(t[o] - m);
    lse = logf(lse);
    #pragma unroll
    for (int o = 0; o < OUTC; ++o) out[(size_t)n * OUTC + o] = t[o] - m - lse;
}

// ---------------- host ----------------
extern "C" void kernel_launch(void* const* d_in, const int* in_sizes, int n_in,
                              void* d_out, int out_size) {
    const float* x      = (const float*)d_in[0];
    const int*   ei     = (const int*)d_in[1];
    const float* Wl     = (const float*)d_in[2];
    const float* Wr     = (const float*)d_in[3];
    const float* att    = (const float*)d_in[4];
    const float* bconv  = (const float*)d_in[5];
    const float* Wlin   = (const float*)d_in[6];
    const float* blin   = (const float*)d_in[7];
    const float* gnw    = (const float*)d_in[8];
    const float* gnb    = (const float*)d_in[9];
    const float* gnms   = (const float*)d_in[10];
    const float* fWl    = (const float*)d_in[11];
    const float* fWr    = (const float*)d_in[12];
    const float* fatt   = (const float*)d_in[13];
    const float* fbconv = (const float*)d_in[14];
    const float* fWlin  = (const float*)d_in[15];
    const float* fblin  = (const float*)d_in[16];
    float* out = (float*)d_out;

    float *p_emb, *p_xl, *p_xr, *p_lin, *p_fxl, *p_fxr, *p_flin, *p_colstat;
    int *p_deg, *p_pos;
    cudaGetSymbolAddress((void**)&p_emb,  g_emb);
    cudaGetSymbolAddress((void**)&p_xl,   g_xl);
    cudaGetSymbolAddress((void**)&p_xr,   g_xr);
    cudaGetSymbolAddress((void**)&p_lin,  g_lin);
    cudaGetSymbolAddress((void**)&p_fxl,  g_fxl);
    cudaGetSymbolAddress((void**)&p_fxr,  g_fxr);
    cudaGetSymbolAddress((void**)&p_flin, g_flin);
    cudaGetSymbolAddress((void**)&p_colstat, g_colstat);
    cudaGetSymbolAddress((void**)&p_deg,  g_deg);
    cudaGetSymbolAddress((void**)&p_pos,  g_pos);

    const int EH_BLOCKS = (EE * HH + 255) / 256;
    const int E_BLOCKS  = (EE + 255) / 256;

    // ---- CSR build ----
    cudaMemsetAsync(p_deg, 0, NN * sizeof(int));
    cudaMemsetAsync(p_pos, 0, NN * sizeof(int));
    k_hist<<<E_BLOCKS, 256>>>(ei);
    k_scan<<<1, 1024>>>();
    k_scatter<<<E_BLOCKS, 256>>>(ei);

    const float* embp = x;
    for (int i = 0; i < 2; ++i) {
        const size_t wo = (size_t)i * DD * DD;
        dim3 grid(6, (NN + 127) / 128);
        k_mma3<<<grid, 256>>>(embp, Wl + wo, Wr + wo, Wlin + wo, blin + i * DD,
                              p_xl, p_xr, p_lin, NN);
        k_edge_score64<<<EH_BLOCKS, 256>>>((const float4*)p_xl, (const float4*)p_xr,
                                           att + i * HH * CC);
        k_softmax_csr<<<(NN + 7) / 8, 256>>>();
        k_agg_csr<<<NN / 4, 256>>>((const float4*)p_xl);
        cudaMemsetAsync(p_colstat, 0, 2 * DD * sizeof(float));
        k_colstats<<<256, 256>>>(bconv + i * DD);
        k_finstats<<<1, 256>>>(gnw + i * DD, gnms + i * DD);
        k_fuse<<<(NN * (DD / 4) + 255) / 256, 256>>>(bconv + i * DD, gnb + i * DD);
        embp = p_emb;
    }

    // final layer
    const int SG_BLOCKS = (NN + 127) / 128;
    k_gemm_small<<<SG_BLOCKS, 256>>>(p_emb, fWl, nullptr, p_fxl, NN, FD);
    k_gemm_small<<<SG_BLOCKS, 256>>>(p_emb, fWr, nullptr, p_fxr, NN, FD);
    k_gemm_small<<<SG_BLOCKS, 256>>>(p_emb, fWlin, fblin, p_flin, NN, OUTC);
    k_edge_score_f<<<EH_BLOCKS, 256>>>(p_fxl, p_fxr, fatt);
    k_softmax_csr<<<(NN + 7) / 8, 256>>>();
    k_agg_csr_f<<<NN / 8, 256>>>();
    k_final<<<(NN + 255) / 256, 256>>>(fbconv, out);
}

// round 8
// speedup vs baseline: 1.3918x; 1.0253x over previous
#include <cuda_runtime.h>
#include <math.h>
#include <stdint.h>

#define NN 50000
#define EE 800000
#define DD 256
#define HH 4
#define CC 64
#define OUTC 5
#define FD (HH*OUTC)   // 20
#define NEG 0.2f
#define GN_EPS 1e-5f
#define SM_EPS 1e-16f

// ---------------- scratch (device globals, no allocation) ----------------
__device__ float g_emb[NN*DD];
__device__ float g_xl [NN*DD];
__device__ float g_xr [NN*DD];
__device__ float g_lin[NN*DD];
__device__ float g_agg[NN*DD];
__device__ float g_score[EE*HH];
__device__ float g_colstat[2*DD];
__device__ float g_mshift[DD];
__device__ float g_rsig  [DD];
__device__ float g_fxl [NN*FD];
__device__ float g_fxr [NN*FD];
__device__ float g_fagg[NN*FD];
__device__ float g_flin[NN*OUTC];
// CSR by destination
__device__ int g_deg[NN];
__device__ int g_off[NN+1];
__device__ int g_pos[NN];
__device__ int g_esrc[EE];
__device__ int g_edst[EE];

static __device__ __forceinline__ float tf32_rn(float x) {
    float r; asm("cvt.rna.tf32.f32 %0, %1;" : "=f"(r) : "f"(x)); return r;
}

#define MMA_TF32(c, a, b)                                                     \
    asm volatile("mma.sync.aligned.m16n8k8.row.col.f32.tf32.tf32.f32 "        \
                 "{%0,%1,%2,%3}, {%4,%5,%6,%7}, {%8,%9}, {%0,%1,%2,%3};"      \
                 : "+f"((c)[0]), "+f"((c)[1]), "+f"((c)[2]), "+f"((c)[3])     \
                 : "r"((a)[0]), "r"((a)[1]), "r"((a)[2]), "r"((a)[3]),        \
                   "r"((b)[0]), "r"((b)[1]))

// ---------------- tensor-core GEMM: 3 outputs in one launch ---------------
// Double-buffered. A raw smem (reg hi/lo split), B hi/lo smem. Stride 136.
#define PADW 136
#define CHF (16*PADW)          // floats per chunk buffer
#define MMA_SMEM (6*CHF*4)     // bytes: 2 bufs x (As,Bh,Bl)

__global__ __launch_bounds__(256, 2)
void k_mma3(const float* __restrict__ A,
            const float* __restrict__ B0, const float* __restrict__ B1,
            const float* __restrict__ B2, const float* __restrict__ bias2,
            float* __restrict__ C0, float* __restrict__ C1,
            float* __restrict__ C2, int M) {
    extern __shared__ float sm[];
    float* AsB = sm;               // [2][16][PADW]
    float* BhB = sm + 2 * CHF;     // [2][16][PADW]
    float* BlB = sm + 4 * CHF;     // [2][16][PADW]

    const int mat = blockIdx.x >> 1;
    const float* __restrict__ B = (mat == 0) ? B0 : (mat == 1) ? B1 : B2;
    float* __restrict__ C = (mat == 0) ? C0 : (mat == 1) ? C1 : C2;
    const float* bias = (mat == 2) ? bias2 : nullptr;

    const int tid = threadIdx.x;
    const int lane = tid & 31, wid = tid >> 5;
    const int warpRow = wid >> 2, warpCol = wid & 3;       // 2 x 4
    const int rowBase = blockIdx.y * 128;
    const int colBase = (blockIdx.x & 1) * 128;

    float c[4][4][4];
    #pragma unroll
    for (int mt = 0; mt < 4; ++mt)
        #pragma unroll
        for (int nt = 0; nt < 4; ++nt)
            #pragma unroll
            for (int j = 0; j < 4; ++j) c[mt][nt][j] = 0.f;

    const int aRow = tid >> 1;
    const int aQ   = (tid & 1) * 2;
    const bool aOk = (rowBase + aRow) < M;
    const int kB = tid >> 5, qB = tid & 31;

    const int mB = warpRow * 64 + (lane >> 2);
    const int nB = warpCol * 32 + (lane >> 2);
    const int kA = lane & 3;

    float4 av[2], bv[2];
    // prologue: chunk 0
    #pragma unroll
    for (int i = 0; i < 2; ++i) {
        av[i] = aOk ? *(const float4*)(A + (size_t)(rowBase + aRow) * 256
                                       + (aQ + i) * 4)
                    : make_float4(0.f, 0.f, 0.f, 0.f);
        bv[i] = *(const float4*)(B + (size_t)(kB + i * 8) * 256 + colBase + qB * 4);
    }
    {
        float* As0 = AsB;
        float* Bh0 = BhB;
        float* Bl0 = BlB;
        #pragma unroll
        for (int i = 0; i < 2; ++i) {
            int q = aQ + i;
            As0[(q*4+0)*PADW + aRow] = av[i].x;
            As0[(q*4+1)*PADW + aRow] = av[i].y;
            As0[(q*4+2)*PADW + aRow] = av[i].z;
            As0[(q*4+3)*PADW + aRow] = av[i].w;
            int k = kB + i * 8;
            float4 v = bv[i], h, l;
            h.x = tf32_rn(v.x); l.x = tf32_rn(v.x - h.x);
            h.y = tf32_rn(v.y); l.y = tf32_rn(v.y - h.y);
            h.z = tf32_rn(v.z); l.z = tf32_rn(v.z - h.z);
            h.w = tf32_rn(v.w); l.w = tf32_rn(v.w - h.w);
            *(float4*)&Bh0[k*PADW + qB*4] = h;
            *(float4*)&Bl0[k*PADW + qB*4] = l;
        }
    }
    __syncthreads();

    for (int ch = 0; ch < 16; ++ch) {
        const int cur = ch & 1, nxt = cur ^ 1;
        if (ch < 15) {
            #pragma unroll
            for (int i = 0; i < 2; ++i) {
                av[i] = aOk ? *(const float4*)(A + (size_t)(rowBase + aRow) * 256
                                               + (ch + 1) * 16 + (aQ + i) * 4)
                            : make_float4(0.f, 0.f, 0.f, 0.f);
                bv[i] = *(const float4*)(B + (size_t)((ch + 1) * 16 + kB + i * 8) * 256
                                         + colBase + qB * 4);
            }
        }
        const float* As = AsB + cur * CHF;
        const float* Bh = BhB + cur * CHF;
        const float* Bl = BlB + cur * CHF;
        #pragma unroll
        for (int ks = 0; ks < 2; ++ks) {
            const int k0 = ks * 8;
            uint32_t bhf[4][2], blf[4][2];
            #pragma unroll
            for (int nt = 0; nt < 4; ++nt) {
                int n = nB + nt * 8;
                bhf[nt][0] = __float_as_uint(Bh[(k0 + kA)*PADW + n]);
                bhf[nt][1] = __float_as_uint(Bh[(k0 + kA + 4)*PADW + n]);
                blf[nt][0] = __float_as_uint(Bl[(k0 + kA)*PADW + n]);
                blf[nt][1] = __float_as_uint(Bl[(k0 + kA + 4)*PADW + n]);
            }
            #pragma unroll
            for (int mt = 0; mt < 4; ++mt) {
                int m = mB + mt * 16;
                float r0 = As[(k0 + kA)*PADW + m];
                float r1 = As[(k0 + kA)*PADW + m + 8];
                float r2 = As[(k0 + kA + 4)*PADW + m];
                float r3 = As[(k0 + kA + 4)*PADW + m + 8];
                float h0 = tf32_rn(r0), h1 = tf32_rn(r1),
                      h2 = tf32_rn(r2), h3 = tf32_rn(r3);
                uint32_t ahi[4] = {__float_as_uint(h0), __float_as_uint(h1),
                                   __float_as_uint(h2), __float_as_uint(h3)};
                uint32_t alo[4] = {__float_as_uint(tf32_rn(r0 - h0)),
                                   __float_as_uint(tf32_rn(r1 - h1)),
                                   __float_as_uint(tf32_rn(r2 - h2)),
                                   __float_as_uint(tf32_rn(r3 - h3))};
                #pragma unroll
                for (int nt = 0; nt < 4; ++nt) {
                    MMA_TF32(c[mt][nt], ahi, bhf[nt]);
                    MMA_TF32(c[mt][nt], ahi, blf[nt]);
                    MMA_TF32(c[mt][nt], alo, bhf[nt]);
                }
            }
        }
        if (ch < 15) {
            float* Asn = AsB + nxt * CHF;
            float* Bhn = BhB + nxt * CHF;
            float* Bln = BlB + nxt * CHF;
            #pragma unroll
            for (int i = 0; i < 2; ++i) {
                int q = aQ + i;
                Asn[(q*4+0)*PADW + aRow] = av[i].x;
                Asn[(q*4+1)*PADW + aRow] = av[i].y;
                Asn[(q*4+2)*PADW + aRow] = av[i].z;
                Asn[(q*4+3)*PADW + aRow] = av[i].w;
                int k = kB + i * 8;
                float4 v = bv[i], h, l;
                h.x = tf32_rn(v.x); l.x = tf32_rn(v.x - h.x);
                h.y = tf32_rn(v.y); l.y = tf32_rn(v.y - h.y);
                h.z = tf32_rn(v.z); l.z = tf32_rn(v.z - h.z);
                h.w = tf32_rn(v.w); l.w = tf32_rn(v.w - h.w);
                *(float4*)&Bhn[k*PADW + qB*4] = h;
                *(float4*)&Bln[k*PADW + qB*4] = l;
            }
            __syncthreads();
        }
    }

    // epilogue
    #pragma unroll
    for (int mt = 0; mt < 4; ++mt) {
        int row = rowBase + warpRow * 64 + mt * 16 + (lane >> 2);
        #pragma unroll
        for (int nt = 0; nt < 4; ++nt) {
            int col = colBase + warpCol * 32 + nt * 8 + (lane & 3) * 2;
            float b0 = bias ? bias[col] : 0.f;
            float b1 = bias ? bias[col + 1] : 0.f;
            if (row < M) {
                float2 o = make_float2(c[mt][nt][0] + b0, c[mt][nt][1] + b1);
                *(float2*)(C + (size_t)row * 256 + col) = o;
            }
            if (row + 8 < M) {
                float2 o = make_float2(c[mt][nt][2] + b0, c[mt][nt][3] + b1);
                *(float2*)(C + (size_t)(row + 8) * 256 + col) = o;
            }
        }
    }
}

// ------- merged final GEMMs: fxl[.,20], fxr[.,20], flin[.,5] in one pass ---
__global__ __launch_bounds__(192)
void k_gemm_f3(const float* __restrict__ A,
               const float* __restrict__ B0, const float* __restrict__ B1,
               const float* __restrict__ B2, const float* __restrict__ bias2,
               float* __restrict__ C0, float* __restrict__ C1,
               float* __restrict__ C2, int M) {
    __shared__ float As[16][129];
    __shared__ float Bs[16][48];
    const int tid = threadIdx.x;
    const int tx = tid % 48, ty = tid / 48;     // 48 cols x 4 row groups
    const int rowBase = blockIdx.x * 128;

    float acc[32];
    #pragma unroll
    for (int r = 0; r < 32; ++r) acc[r] = 0.f;

    for (int ch = 0; ch < 16; ++ch) {
        for (int i = tid; i < 2048; i += 192) {
            int row = i >> 4, k = i & 15;
            int gr = rowBase + row;
            As[k][row] = (gr < M) ? A[(size_t)gr * 256 + ch * 16 + k] : 0.f;
        }
        for (int i = tid; i < 768; i += 192) {
            int k = i / 48, cc = i % 48;
            float v = 0.f;
            int gk = ch * 16 + k;
            if (cc < FD)            v = B0[(size_t)gk * FD + cc];
            else if (cc < 2 * FD)   v = B1[(size_t)gk * FD + (cc - FD)];
            else if (cc < 2 * FD + OUTC) v = B2[(size_t)gk * OUTC + (cc - 2 * FD)];
            Bs[k][cc] = v;
        }
        __syncthreads();
        #pragma unroll
        for (int k = 0; k < 16; ++k) {
            float b = Bs[k][tx];
            #pragma unroll
            for (int r = 0; r < 32; ++r) acc[r] += As[k][ty * 32 + r] * b;
        }
        __syncthreads();
    }

    #pragma unroll
    for (int r = 0; r < 32; ++r) {
        int row = rowBase + ty * 32 + r;
        if (row >= M) break;
        if (tx < FD) {
            C0[(size_t)row * FD + tx] = acc[r];
        } else if (tx < 2 * FD) {
            C1[(size_t)row * FD + (tx - FD)] = acc[r];
        } else if (tx < 2 * FD + OUTC) {
            C2[(size_t)row * OUTC + (tx - 2 * FD)] = acc[r] + bias2[tx - 2 * FD];
        }
    }
}

// ---------------- CSR build ----------------
__global__ void k_hist(const int* __restrict__ ei) {
    int e = blockIdx.x * blockDim.x + threadIdx.x;
    if (e < EE) atomicAdd(&g_deg[ei[EE + e]], 1);
}

__global__ void k_scan() {
    __shared__ int wsum[32];
    const int CH = 49;
    int t = threadIdx.x;
    int base = t * CH;
    int s = 0;
    for (int i = 0; i < CH; ++i) {
        int idx = base + i;
        if (idx < NN) s += g_deg[idx];
    }
    int lane = t & 31, wid = t >> 5;
    int v = s;
    #pragma unroll
    for (int d = 1; d < 32; d <<= 1) {
        int n = __shfl_up_sync(~0u, v, d);
        if (lane >= d) v += n;
    }
    if (lane == 31) wsum[wid] = v;
    __syncthreads();
    if (wid == 0) {
        int wv = wsum[lane];
        #pragma unroll
        for (int d = 1; d < 32; d <<= 1) {
            int n = __shfl_up_sync(~0u, wv, d);
            if (lane >= d) wv += n;
        }
        wsum[lane] = wv;
    }
    __syncthreads();
    int pre = (v - s) + (wid > 0 ? wsum[wid - 1] : 0);
    for (int i = 0; i < CH; ++i) {
        int idx = base + i;
        if (idx < NN) { g_off[idx] = pre; pre += g_deg[idx]; }
    }
    if (t == 1023) g_off[NN] = pre;
}

__global__ void k_scatter(const int* __restrict__ ei) {
    int e = blockIdx.x * blockDim.x + threadIdx.x;
    if (e >= EE) return;
    int src = ei[e], dst = ei[EE + e];
    int p = atomicAdd(&g_pos[dst], 1);
    int slot = g_off[dst] + p;
    g_esrc[slot] = src;
    g_edst[slot] = dst;
}

// ---------------- edge scoring (CSR slot order) ----------------
__global__ void k_edge_score64(const float4* __restrict__ xl,
                               const float4* __restrict__ xr,
                               const float* __restrict__ att) {
    __shared__ float4 satt[64];
    int tid = threadIdx.x;
    if (tid < 64) satt[tid] = ((const float4*)att)[tid];
    __syncthreads();
    int idx = blockIdx.x * 256 + tid;
    if (idx >= EE * HH) return;
    int j = idx >> 2, h = idx & 3;
    int src = g_esrc[j], dst = g_edst[j];
    const float4* pl = xl + (size_t)src * 64 + h * 16;
    const float4* pr = xr + (size_t)dst * 64 + h * 16;
    float s = 0.f;
    #pragma unroll
    for (int g = 0; g < 16; ++g) {
        float4 a = pl[g], b = pr[g], w = satt[h * 16 + g];
        float v;
        v = a.x + b.x; v = v > 0.f ? v : NEG * v; s += w.x * v;
        v = a.y + b.y; v = v > 0.f ? v : NEG * v; s += w.y * v;
        v = a.z + b.z; v = v > 0.f ? v : NEG * v; s += w.z * v;
        v = a.w + b.w; v = v > 0.f ? v : NEG * v; s += w.w * v;
    }
    g_score[idx] = s;
}

__global__ void k_edge_score_f(const float* __restrict__ xl,
                               const float* __restrict__ xr,
                               const float* __restrict__ att) {
    int idx = blockIdx.x * blockDim.x + threadIdx.x;
    if (idx >= EE * HH) return;
    int j = idx >> 2, h = idx & 3;
    int src = g_esrc[j], dst = g_edst[j];
    const float* pl = xl + (size_t)src * FD + h * OUTC;
    const float* pr = xr + (size_t)dst * FD + h * OUTC;
    const float* pa = att + h * OUTC;
    float s = 0.f;
    #pragma unroll
    for (int c = 0; c < OUTC; ++c) {
        float v = pl[c] + pr[c];
        v = v > 0.f ? v : NEG * v;
        s += pa[c] * v;
    }
    g_score[idx] = s;
}

// ---------------- segment softmax ----------------
__global__ void k_softmax_csr() {
    int w = (blockIdx.x * blockDim.x + threadIdx.x) >> 5;
    if (w >= NN) return;
    int lane = threadIdx.x & 31;
    int beg = g_off[w], end = g_off[w + 1];
    int h = lane & 3;
    int j0 = beg + (lane >> 2);

    float m = -1e30f;
    for (int j = j0; j < end; j += 8) m = fmaxf(m, g_score[j * 4 + h]);
    #pragma unroll
    for (int d = 4; d < 32; d <<= 1) m = fmaxf(m, __shfl_xor_sync(~0u, m, d));

    float den = 0.f;
    for (int j = j0; j < end; j += 8) den += __expf(g_score[j * 4 + h] - m);
    #pragma unroll
    for (int d = 4; d < 32; d <<= 1) den += __shfl_xor_sync(~0u, den, d);
    float inv = 1.f / (den + SM_EPS);

    for (int j = j0; j < end; j += 8)
        g_score[j * 4 + h] = __expf(g_score[j * 4 + h] - m) * inv;
}

// ---------------- aggregation (gather) ----------------
__global__ void k_agg_csr(const float4* __restrict__ xl) {
    int node = blockIdx.x * 4 + (threadIdx.x >> 6);
    int t = threadIdx.x & 63;
    int h = t >> 4;
    int beg = g_off[node], end = g_off[node + 1];
    float4 acc = make_float4(0.f, 0.f, 0.f, 0.f);
    for (int j = beg; j < end; ++j) {
        int src = g_esrc[j];
        float a = g_score[j * 4 + h];
        float4 v = xl[(size_t)src * 64 + t];
        acc.x += a * v.x; acc.y += a * v.y; acc.z += a * v.z; acc.w += a * v.w;
    }
    ((float4*)g_agg)[(size_t)node * 64 + t] = acc;
}

__global__ void k_agg_csr_f() {
    int node = blockIdx.x * 8 + (threadIdx.x >> 5);
    int t = threadIdx.x & 31;
    if (t >= FD) return;
    int h = t / OUTC;
    int beg = g_off[node], end = g_off[node + 1];
    float acc = 0.f;
    for (int j = beg; j < end; ++j) {
        int src = g_esrc[j];
        acc += g_score[j * 4 + h] * g_fxl[(size_t)src * FD + t];
    }
    g_fagg[(size_t)node * FD + t] = acc;
}

// ---------------- GraphNorm ----------------
__global__ void k_colstats(const float* __restrict__ bconv) {
    int t = threadIdx.x;
    float bc = bconv[t];
    float s = 0.f, q = 0.f;
    for (int r = blockIdx.x; r < NN; r += gridDim.x) {
        float v = g_agg[(size_t)r * DD + t] + bc;
        s += v; q += v * v;
    }
    atomicAdd(&g_colstat[t], s);
    atomicAdd(&g_colstat[DD + t], q);
}

__global__ void k_finstats(const float* __restrict__ gnw, const float* __restrict__ gnms) {
    int t = threadIdx.x;
    float mean = g_colstat[t] * (1.f / NN);
    float ms = mean * gnms[t];
    float var = g_colstat[DD + t] * (1.f / NN) - 2.f * ms * mean + ms * ms;
    g_mshift[t] = ms;
    g_rsig[t] = gnw[t] * rsqrtf(var + GN_EPS);
}

__global__ void k_fuse(const float* __restrict__ bconv, const float* __restrict__ gnb) {
    int i = blockIdx.x * blockDim.x + threadIdx.x;
    if (i >= NN * (DD / 4)) return;
    int c4 = (i & 63) * 4;
    float4 v = ((const float4*)g_agg)[i];
    float4 l = ((const float4*)g_lin)[i];
    float4 r;
    float t;
    t = (v.x + bconv[c4+0] - g_mshift[c4+0]) * g_rsig[c4+0] + gnb[c4+0] + l.x;
    r.x = t > 0.f ? t : expm1f(t);
    t = (v.y + bconv[c4+1] - g_mshift[c4+1]) * g_rsig[c4+1] + gnb[c4+1] + l.y;
    r.y = t > 0.f ? t : expm1f(t);
    t = (v.z + bconv[c4+2] - g_mshift[c4+2]) * g_rsig[c4+2] + gnb[c4+2] + l.z;
    r.z = t > 0.f ? t : expm1f(t);
    t = (v.w + bconv[c4+3] - g_mshift[c4+3]) * g_rsig[c4+3] + gnb[c4+3] + l.w;
    r.w = t > 0.f ? t : expm1f(t);
    ((float4*)g_emb)[i] = r;
}

// ---------------- final combine + log_softmax ----------------
__global__ void k_final(const float* __restrict__ fbconv, float* __restrict__ out) {
    int n = blockIdx.x * blockDim.x + threadIdx.x;
    if (n >= NN) return;
    float t[OUTC];
    #pragma unroll
    for (int o = 0; o < OUTC; ++o) {
        float s = 0.f;
        #pragma unroll
        for (int h = 0; h < HH; ++h) s += g_fagg[(size_t)n * FD + h * OUTC + o];
        t[o] = 0.25f * s + fbconv[o] + g_flin[(size_t)n * OUTC + o];
    }
    float m = t[0];
    #pragma unroll
    for (int o = 1; o < OUTC; ++o) m = fmaxf(m, t[o]);
    float lse = 0.f;
    #pragma unroll
    for (int o = 0; o < OUTC; ++o) lse += expf(t[o] - m);
    lse = logf(lse);
    #pragma unroll
    for (int o = 0; o < OUTC; ++o) out[(size_t)n * OUTC + o] = t[o] - m - lse;
}

// ---------------- host ----------------
extern "C" void kernel_launch(void* const* d_in, const int* in_sizes, int n_in,
                              void* d_out, int out_size) {
    const float* x      = (const float*)d_in[0];
    const int*   ei     = (const int*)d_in[1];
    const float* Wl     = (const float*)d_in[2];
    const float* Wr     = (const float*)d_in[3];
    const float* att    = (const float*)d_in[4];
    const float* bconv  = (const float*)d_in[5];
    const float* Wlin   = (const float*)d_in[6];
    const float* blin   = (const float*)d_in[7];
    const float* gnw    = (const float*)d_in[8];
    const float* gnb    = (const float*)d_in[9];
    const float* gnms   = (const float*)d_in[10];
    const float* fWl    = (const float*)d_in[11];
    const float* fWr    = (const float*)d_in[12];
    const float* fatt   = (const float*)d_in[13];
    const float* fbconv = (const float*)d_in[14];
    const float* fWlin  = (const float*)d_in[15];
    const float* fblin  = (const float*)d_in[16];
    float* out = (float*)d_out;

    cudaFuncSetAttribute(k_mma3, cudaFuncAttributeMaxDynamicSharedMemorySize,
                         MMA_SMEM);

    float *p_emb, *p_xl, *p_xr, *p_lin, *p_fxl, *p_fxr, *p_flin, *p_colstat;
    int *p_deg, *p_pos;
    cudaGetSymbolAddress((void**)&p_emb,  g_emb);
    cudaGetSymbolAddress((void**)&p_xl,   g_xl);
    cudaGetSymbolAddress((void**)&p_xr,   g_xr);
    cudaGetSymbolAddress((void**)&p_lin,  g_lin);
    cudaGetSymbolAddress((void**)&p_fxl,  g_fxl);
    cudaGetSymbolAddress((void**)&p_fxr,  g_fxr);
    cudaGetSymbolAddress((void**)&p_flin, g_flin);
    cudaGetSymbolAddress((void**)&p_colstat, g_colstat);
    cudaGetSymbolAddress((void**)&p_deg,  g_deg);
    cudaGetSymbolAddress((void**)&p_pos,  g_pos);

    const int EH_BLOCKS = (EE * HH + 255) / 256;
    const int E_BLOCKS  = (EE + 255) / 256;

    // ---- CSR build ----
    cudaMemsetAsync(p_deg, 0, NN * sizeof(int));
    cudaMemsetAsync(p_pos, 0, NN * sizeof(int));
    k_hist<<<E_BLOCKS, 256>>>(ei);
    k_scan<<<1, 1024>>>();
    k_scatter<<<E_BLOCKS, 256>>>(ei);

    const float* embp = x;
    for (int i = 0; i < 2; ++i) {
        const size_t wo = (size_t)i * DD * DD;
        dim3 grid(6, (NN + 127) / 128);
        k_mma3<<<grid, 256, MMA_SMEM>>>(embp, Wl + wo, Wr + wo, Wlin + wo,
                                        blin + i * DD, p_xl, p_xr, p_lin, NN);
        k_edge_score64<<<EH_BLOCKS, 256>>>((const float4*)p_xl, (const float4*)p_xr,
                                           att + i * HH * CC);
        k_softmax_csr<<<(NN + 7) / 8, 256>>>();
        k_agg_csr<<<NN / 4, 256>>>((const float4*)p_xl);
        cudaMemsetAsync(p_colstat, 0, 2 * DD * sizeof(float));
        k_colstats<<<256, 256>>>(bconv + i * DD);
        k_finstats<<<1, 256>>>(gnw + i * DD, gnms + i * DD);
        k_fuse<<<(NN * (DD / 4) + 255) / 256, 256>>>(bconv + i * DD, gnb + i * DD);
        embp = p_emb;
    }

    // final layer (merged small GEMMs)
    k_gemm_f3<<<(NN + 127) / 128, 192>>>(p_emb, fWl, fWr, fWlin, fblin,
                                         p_fxl, p_fxr, p_flin, NN);
    k_edge_score_f<<<EH_BLOCKS, 256>>>(p_fxl, p_fxr, fatt);
    k_softmax_csr<<<(NN + 7) / 8, 256>>>();
    k_agg_csr_f<<<NN / 8, 256>>>();
    k_final<<<(NN + 255) / 256, 256>>>(fbconv, out);
}

// round 9
// speedup vs baseline: 1.5918x; 1.1437x over previous
#include <cuda_runtime.h>
#include <cuda_bf16.h>
#include <math.h>
#include <stdint.h>

#define NN 50000
#define EE 800000
#define DD 256
#define HH 4
#define CC 64
#define OUTC 5
#define FD (HH*OUTC)   // 20
#define NEG 0.2f
#define GN_EPS 1e-5f
#define SM_EPS 1e-16f

// ---------------- scratch (device globals, no allocation) ----------------
__device__ float g_emb[NN*DD];
__device__ float g_xl [NN*DD];
__device__ float g_xr [NN*DD];
__device__ float g_lin[NN*DD];
__device__ float g_agg[NN*DD];
__device__ float g_score[EE*HH];
__device__ float g_colstat[2*DD];
__device__ float g_mshift[DD];
__device__ float g_rsig  [DD];
__device__ float g_fxl [NN*FD];
__device__ float g_fxr [NN*FD];
__device__ float g_fagg[NN*FD];
__device__ float g_flin[NN*OUTC];
// CSR by destination
__device__ int g_deg[NN];
__device__ int g_off[NN+1];
__device__ int g_pos[NN];
__device__ int g_esrc[EE];
__device__ int g_edst[EE];

#define MMA_BF16(c, a, b)                                                     \
    asm volatile("mma.sync.aligned.m16n8k16.row.col.f32.bf16.bf16.f32 "       \
                 "{%0,%1,%2,%3}, {%4,%5,%6,%7}, {%8,%9}, {%0,%1,%2,%3};"      \
                 : "+f"((c)[0]), "+f"((c)[1]), "+f"((c)[2]), "+f"((c)[3])     \
                 : "r"((a)[0]), "r"((a)[1]), "r"((a)[2]), "r"((a)[3]),        \
                   "r"((b)[0]), "r"((b)[1]))

// split two floats into packed bf16x2 hi and lo (k-even in low half)
static __device__ __forceinline__ void split2(float a, float b,
                                              uint32_t& hi, uint32_t& lo) {
    __nv_bfloat16 ha = __float2bfloat16(a), hb = __float2bfloat16(b);
    float ra = a - __bfloat162float(ha);
    float rb = b - __bfloat162float(hb);
    __nv_bfloat16 la = __float2bfloat16(ra), lb = __float2bfloat16(rb);
    hi = ((uint32_t)__bfloat16_as_ushort(hb) << 16) | __bfloat16_as_ushort(ha);
    lo = ((uint32_t)__bfloat16_as_ushort(lb) << 16) | __bfloat16_as_ushort(la);
}

// ---------------- tensor-core GEMM: 3 outputs in one launch ---------------
// 3xBF16 compensation (hi*hi + hi*lo + lo*hi), m16n8k16. Double-buffered.
// Packed bf16x2 smem: [kp][m] / [kp][n], kp pairs adjacent k. Stride 136.
#define PADW 136
#define CHU (8*PADW)            // uint32 per chunk buffer
#define MMA_SMEM (8*CHU*4)      // bytes: 2 bufs x (Ah,Al,Bh,Bl)

__global__ __launch_bounds__(256, 2)
void k_mma3(const float* __restrict__ A,
            const float* __restrict__ B0, const float* __restrict__ B1,
            const float* __restrict__ B2, const float* __restrict__ bias2,
            float* __restrict__ C0, float* __restrict__ C1,
            float* __restrict__ C2, int M) {
    extern __shared__ uint32_t smu[];
    uint32_t* AhB = smu;             // [2][8][PADW]
    uint32_t* AlB = smu + 2 * CHU;
    uint32_t* BhB = smu + 4 * CHU;
    uint32_t* BlB = smu + 6 * CHU;

    const int mat = blockIdx.x >> 1;
    const float* __restrict__ B = (mat == 0) ? B0 : (mat == 1) ? B1 : B2;
    float* __restrict__ C = (mat == 0) ? C0 : (mat == 1) ? C1 : C2;
    const float* bias = (mat == 2) ? bias2 : nullptr;

    const int tid = threadIdx.x;
    const int lane = tid & 31, wid = tid >> 5;
    const int warpRow = wid >> 2, warpCol = wid & 3;       // 2 x 4
    const int rowBase = blockIdx.y * 128;
    const int colBase = (blockIdx.x & 1) * 128;

    float c[4][4][4];
    #pragma unroll
    for (int mt = 0; mt < 4; ++mt)
        #pragma unroll
        for (int nt = 0; nt < 4; ++nt)
            #pragma unroll
            for (int j = 0; j < 4; ++j) c[mt][nt][j] = 0.f;

    // A fill: thread -> row aRow, k-half aHalf (8 k = 4 kp)
    const int aRow = tid >> 1;
    const int aHalf = tid & 1;
    const bool aOk = (rowBase + aRow) < M;
    // B fill: thread -> kp (0..7), col quad qB
    const int kpB = tid >> 5, qB = tid & 31;

    const int gid = lane >> 2;   // 0..7
    const int tig = lane & 3;    // 0..3

    float4 av0, av1, bv0, bv1;
    // prologue: chunk 0 loads
    av0 = aOk ? *(const float4*)(A + (size_t)(rowBase + aRow) * 256 + aHalf * 8)
              : make_float4(0.f, 0.f, 0.f, 0.f);
    av1 = aOk ? *(const float4*)(A + (size_t)(rowBase + aRow) * 256 + aHalf * 8 + 4)
              : make_float4(0.f, 0.f, 0.f, 0.f);
    bv0 = *(const float4*)(B + (size_t)(2 * kpB) * 256 + colBase + qB * 4);
    bv1 = *(const float4*)(B + (size_t)(2 * kpB + 1) * 256 + colBase + qB * 4);
    {
        uint32_t h, l;
        int kb = aHalf * 4;
        split2(av0.x, av0.y, h, l); AhB[(kb+0)*PADW + aRow] = h; AlB[(kb+0)*PADW + aRow] = l;
        split2(av0.z, av0.w, h, l); AhB[(kb+1)*PADW + aRow] = h; AlB[(kb+1)*PADW + aRow] = l;
        split2(av1.x, av1.y, h, l); AhB[(kb+2)*PADW + aRow] = h; AlB[(kb+2)*PADW + aRow] = l;
        split2(av1.z, av1.w, h, l); AhB[(kb+3)*PADW + aRow] = h; AlB[(kb+3)*PADW + aRow] = l;
        split2(bv0.x, bv1.x, h, l); BhB[kpB*PADW + qB*4+0] = h; BlB[kpB*PADW + qB*4+0] = l;
        split2(bv0.y, bv1.y, h, l); BhB[kpB*PADW + qB*4+1] = h; BlB[kpB*PADW + qB*4+1] = l;
        split2(bv0.z, bv1.z, h, l); BhB[kpB*PADW + qB*4+2] = h; BlB[kpB*PADW + qB*4+2] = l;
        split2(bv0.w, bv1.w, h, l); BhB[kpB*PADW + qB*4+3] = h; BlB[kpB*PADW + qB*4+3] = l;
    }
    __syncthreads();

    for (int ch = 0; ch < 16; ++ch) {
        const int cur = ch & 1, nxt = cur ^ 1;
        if (ch < 15) {
            const int kg = (ch + 1) * 16;
            av0 = aOk ? *(const float4*)(A + (size_t)(rowBase + aRow) * 256 + kg + aHalf * 8)
                      : make_float4(0.f, 0.f, 0.f, 0.f);
            av1 = aOk ? *(const float4*)(A + (size_t)(rowBase + aRow) * 256 + kg + aHalf * 8 + 4)
                      : make_float4(0.f, 0.f, 0.f, 0.f);
            bv0 = *(const float4*)(B + (size_t)(kg + 2 * kpB) * 256 + colBase + qB * 4);
            bv1 = *(const float4*)(B + (size_t)(kg + 2 * kpB + 1) * 256 + colBase + qB * 4);
        }
        const uint32_t* Ah = AhB + cur * CHU;
        const uint32_t* Al = AlB + cur * CHU;
        const uint32_t* Bh = BhB + cur * CHU;
        const uint32_t* Bl = BlB + cur * CHU;

        uint32_t bhf[4][2], blf[4][2];
        #pragma unroll
        for (int nt = 0; nt < 4; ++nt) {
            int n = warpCol * 32 + nt * 8 + gid;
            bhf[nt][0] = Bh[tig*PADW + n];
            bhf[nt][1] = Bh[(tig+4)*PADW + n];
            blf[nt][0] = Bl[tig*PADW + n];
            blf[nt][1] = Bl[(tig+4)*PADW + n];
        }
        #pragma unroll
        for (int mt = 0; mt < 4; ++mt) {
            int m = warpRow * 64 + mt * 16 + gid;
            uint32_t ahi[4], alo[4];
            ahi[0] = Ah[tig*PADW + m];
            ahi[1] = Ah[tig*PADW + m + 8];
            ahi[2] = Ah[(tig+4)*PADW + m];
            ahi[3] = Ah[(tig+4)*PADW + m + 8];
            alo[0] = Al[tig*PADW + m];
            alo[1] = Al[tig*PADW + m + 8];
            alo[2] = Al[(tig+4)*PADW + m];
            alo[3] = Al[(tig+4)*PADW + m + 8];
            #pragma unroll
            for (int nt = 0; nt < 4; ++nt) {
                MMA_BF16(c[mt][nt], ahi, bhf[nt]);
                MMA_BF16(c[mt][nt], ahi, blf[nt]);
                MMA_BF16(c[mt][nt], alo, bhf[nt]);
            }
        }
        if (ch < 15) {
            uint32_t* Ahn = AhB + nxt * CHU;
            uint32_t* Aln = AlB + nxt * CHU;
            uint32_t* Bhn = BhB + nxt * CHU;
            uint32_t* Bln = BlB + nxt * CHU;
            uint32_t h, l;
            int kb = aHalf * 4;
            split2(av0.x, av0.y, h, l); Ahn[(kb+0)*PADW + aRow] = h; Aln[(kb+0)*PADW + aRow] = l;
            split2(av0.z, av0.w, h, l); Ahn[(kb+1)*PADW + aRow] = h; Aln[(kb+1)*PADW + aRow] = l;
            split2(av1.x, av1.y, h, l); Ahn[(kb+2)*PADW + aRow] = h; Aln[(kb+2)*PADW + aRow] = l;
            split2(av1.z, av1.w, h, l); Ahn[(kb+3)*PADW + aRow] = h; Aln[(kb+3)*PADW + aRow] = l;
            split2(bv0.x, bv1.x, h, l); Bhn[kpB*PADW + qB*4+0] = h; Bln[kpB*PADW + qB*4+0] = l;
            split2(bv0.y, bv1.y, h, l); Bhn[kpB*PADW + qB*4+1] = h; Bln[kpB*PADW + qB*4+1] = l;
            split2(bv0.z, bv1.z, h, l); Bhn[kpB*PADW + qB*4+2] = h; Bln[kpB*PADW + qB*4+2] = l;
            split2(bv0.w, bv1.w, h, l); Bhn[kpB*PADW + qB*4+3] = h; Bln[kpB*PADW + qB*4+3] = l;
            __syncthreads();
        }
    }

    // epilogue (same fragment->row/col map as m16n8k8)
    #pragma unroll
    for (int mt = 0; mt < 4; ++mt) {
        int row = rowBase + warpRow * 64 + mt * 16 + gid;
        #pragma unroll
        for (int nt = 0; nt < 4; ++nt) {
            int col = colBase + warpCol * 32 + nt * 8 + tig * 2;
            float b0 = bias ? bias[col] : 0.f;
            float b1 = bias ? bias[col + 1] : 0.f;
            if (row < M) {
                float2 o = make_float2(c[mt][nt][0] + b0, c[mt][nt][1] + b1);
                *(float2*)(C + (size_t)row * 256 + col) = o;
            }
            if (row + 8 < M) {
                float2 o = make_float2(c[mt][nt][2] + b0, c[mt][nt][3] + b1);
                *(float2*)(C + (size_t)(row + 8) * 256 + col) = o;
            }
        }
    }
}

// ------- merged final GEMMs: fxl[.,20], fxr[.,20], flin[.,5] in one pass ---
__global__ __launch_bounds__(192)
void k_gemm_f3(const float* __restrict__ A,
               const float* __restrict__ B0, const float* __restrict__ B1,
               const float* __restrict__ B2, const float* __restrict__ bias2,
               float* __restrict__ C0, float* __restrict__ C1,
               float* __restrict__ C2, int M) {
    __shared__ float As[16][129];
    __shared__ float Bs[16][48];
    const int tid = threadIdx.x;
    const int tx = tid % 48, ty = tid / 48;
    const int rowBase = blockIdx.x * 128;

    float acc[32];
    #pragma unroll
    for (int r = 0; r < 32; ++r) acc[r] = 0.f;

    for (int ch = 0; ch < 16; ++ch) {
        for (int i = tid; i < 2048; i += 192) {
            int row = i >> 4, k = i & 15;
            int gr = rowBase + row;
            As[k][row] = (gr < M) ? A[(size_t)gr * 256 + ch * 16 + k] : 0.f;
        }
        for (int i = tid; i < 768; i += 192) {
            int k = i / 48, cc = i % 48;
            float v = 0.f;
            int gk = ch * 16 + k;
            if (cc < FD)            v = B0[(size_t)gk * FD + cc];
            else if (cc < 2 * FD)   v = B1[(size_t)gk * FD + (cc - FD)];
            else if (cc < 2 * FD + OUTC) v = B2[(size_t)gk * OUTC + (cc - 2 * FD)];
            Bs[k][cc] = v;
        }
        __syncthreads();
        #pragma unroll
        for (int k = 0; k < 16; ++k) {
            float b = Bs[k][tx];
            #pragma unroll
            for (int r = 0; r < 32; ++r) acc[r] += As[k][ty * 32 + r] * b;
        }
        __syncthreads();
    }

    #pragma unroll
    for (int r = 0; r < 32; ++r) {
        int row = rowBase + ty * 32 + r;
        if (row >= M) break;
        if (tx < FD) {
            C0[(size_t)row * FD + tx] = acc[r];
        } else if (tx < 2 * FD) {
            C1[(size_t)row * FD + (tx - FD)] = acc[r];
        } else if (tx < 2 * FD + OUTC) {
            C2[(size_t)row * OUTC + (tx - 2 * FD)] = acc[r] + bias2[tx - 2 * FD];
        }
    }
}

// ---------------- CSR build ----------------
__global__ void k_hist(const int* __restrict__ ei) {
    int e = blockIdx.x * blockDim.x + threadIdx.x;
    if (e < EE) atomicAdd(&g_deg[ei[EE + e]], 1);
}

__global__ void k_scan() {
    __shared__ int wsum[32];
    const int CH = 49;
    int t = threadIdx.x;
    int base = t * CH;
    int s = 0;
    for (int i = 0; i < CH; ++i) {
        int idx = base + i;
        if (idx < NN) s += g_deg[idx];
    }
    int lane = t & 31, wid = t >> 5;
    int v = s;
    #pragma unroll
    for (int d = 1; d < 32; d <<= 1) {
        int n = __shfl_up_sync(~0u, v, d);
        if (lane >= d) v += n;
    }
    if (lane == 31) wsum[wid] = v;
    __syncthreads();
    if (wid == 0) {
        int wv = wsum[lane];
        #pragma unroll
        for (int d = 1; d < 32; d <<= 1) {
            int n = __shfl_up_sync(~0u, wv, d);
            if (lane >= d) wv += n;
        }
        wsum[lane] = wv;
    }
    __syncthreads();
    int pre = (v - s) + (wid > 0 ? wsum[wid - 1] : 0);
    for (int i = 0; i < CH; ++i) {
        int idx = base + i;
        if (idx < NN) { g_off[idx] = pre; pre += g_deg[idx]; }
    }
    if (t == 1023) g_off[NN] = pre;
}

__global__ void k_scatter(const int* __restrict__ ei) {
    int e = blockIdx.x * blockDim.x + threadIdx.x;
    if (e >= EE) return;
    int src = ei[e], dst = ei[EE + e];
    int p = atomicAdd(&g_pos[dst], 1);
    int slot = g_off[dst] + p;
    g_esrc[slot] = src;
    g_edst[slot] = dst;
}

// ---------------- edge scoring (CSR slot order) ----------------
__global__ void k_edge_score64(const float4* __restrict__ xl,
                               const float4* __restrict__ xr,
                               const float* __restrict__ att) {
    __shared__ float4 satt[64];
    int tid = threadIdx.x;
    if (tid < 64) satt[tid] = ((const float4*)att)[tid];
    __syncthreads();
    int idx = blockIdx.x * 256 + tid;
    if (idx >= EE * HH) return;
    int j = idx >> 2, h = idx & 3;
    int src = g_esrc[j], dst = g_edst[j];
    const float4* pl = xl + (size_t)src * 64 + h * 16;
    const float4* pr = xr + (size_t)dst * 64 + h * 16;
    float s = 0.f;
    #pragma unroll
    for (int g = 0; g < 16; ++g) {
        float4 a = pl[g], b = pr[g], w = satt[h * 16 + g];
        float v;
        v = a.x + b.x; v = v > 0.f ? v : NEG * v; s += w.x * v;
        v = a.y + b.y; v = v > 0.f ? v : NEG * v; s += w.y * v;
        v = a.z + b.z; v = v > 0.f ? v : NEG * v; s += w.z * v;
        v = a.w + b.w; v = v > 0.f ? v : NEG * v; s += w.w * v;
    }
    g_score[idx] = s;
}

__global__ void k_edge_score_f(const float* __restrict__ xl,
                               const float* __restrict__ xr,
                               const float* __restrict__ att) {
    int idx = blockIdx.x * blockDim.x + threadIdx.x;
    if (idx >= EE * HH) return;
    int j = idx >> 2, h = idx & 3;
    int src = g_esrc[j], dst = g_edst[j];
    const float* pl = xl + (size_t)src * FD + h * OUTC;
    const float* pr = xr + (size_t)dst * FD + h * OUTC;
    const float* pa = att + h * OUTC;
    float s = 0.f;
    #pragma unroll
    for (int c = 0; c < OUTC; ++c) {
        float v = pl[c] + pr[c];
        v = v > 0.f ? v : NEG * v;
        s += pa[c] * v;
    }
    g_score[idx] = s;
}

// ---------------- segment softmax ----------------
__global__ void k_softmax_csr() {
    int w = (blockIdx.x * blockDim.x + threadIdx.x) >> 5;
    if (w >= NN) return;
    int lane = threadIdx.x & 31;
    int beg = g_off[w], end = g_off[w + 1];
    int h = lane & 3;
    int j0 = beg + (lane >> 2);

    float m = -1e30f;
    for (int j = j0; j < end; j += 8) m = fmaxf(m, g_score[j * 4 + h]);
    #pragma unroll
    for (int d = 4; d < 32; d <<= 1) m = fmaxf(m, __shfl_xor_sync(~0u, m, d));

    float den = 0.f;
    for (int j = j0; j < end; j += 8) den += __expf(g_score[j * 4 + h] - m);
    #pragma unroll
    for (int d = 4; d < 32; d <<= 1) den += __shfl_xor_sync(~0u, den, d);
    float inv = 1.f / (den + SM_EPS);

    for (int j = j0; j < end; j += 8)
        g_score[j * 4 + h] = __expf(g_score[j * 4 + h] - m) * inv;
}

// ---------------- aggregation (gather) ----------------
__global__ void k_agg_csr(const float4* __restrict__ xl) {
    int node = blockIdx.x * 4 + (threadIdx.x >> 6);
    int t = threadIdx.x & 63;
    int h = t >> 4;
    int beg = g_off[node], end = g_off[node + 1];
    float4 acc = make_float4(0.f, 0.f, 0.f, 0.f);
    for (int j = beg; j < end; ++j) {
        int src = g_esrc[j];
        float a = g_score[j * 4 + h];
        float4 v = xl[(size_t)src * 64 + t];
        acc.x += a * v.x; acc.y += a * v.y; acc.z += a * v.z; acc.w += a * v.w;
    }
    ((float4*)g_agg)[(size_t)node * 64 + t] = acc;
}

__global__ void k_agg_csr_f() {
    int node = blockIdx.x * 8 + (threadIdx.x >> 5);
    int t = threadIdx.x & 31;
    if (t >= FD) return;
    int h = t / OUTC;
    int beg = g_off[node], end = g_off[node + 1];
    float acc = 0.f;
    for (int j = beg; j < end; ++j) {
        int src = g_esrc[j];
        acc += g_score[j * 4 + h] * g_fxl[(size_t)src * FD + t];
    }
    g_fagg[(size_t)node * FD + t] = acc;
}

// ---------------- GraphNorm ----------------
__global__ void k_colstats(const float* __restrict__ bconv) {
    int t = threadIdx.x;
    float bc = bconv[t];
    float s = 0.f, q = 0.f;
    for (int r = blockIdx.x; r < NN; r += gridDim.x) {
        float v = g_agg[(size_t)r * DD + t] + bc;
        s += v; q += v * v;
    }
    atomicAdd(&g_colstat[t], s);
    atomicAdd(&g_colstat[DD + t], q);
}

__global__ void k_finstats(const float* __restrict__ gnw, const float* __restrict__ gnms) {
    int t = threadIdx.x;
    float mean = g_colstat[t] * (1.f / NN);
    float ms = mean * gnms[t];
    float var = g_colstat[DD + t] * (1.f / NN) - 2.f * ms * mean + ms * ms;
    g_mshift[t] = ms;
    g_rsig[t] = gnw[t] * rsqrtf(var + GN_EPS);
}

__global__ void k_fuse(const float* __restrict__ bconv, const float* __restrict__ gnb) {
    int i = blockIdx.x * blockDim.x + threadIdx.x;
    if (i >= NN * (DD / 4)) return;
    int c4 = (i & 63) * 4;
    float4 v = ((const float4*)g_agg)[i];
    float4 l = ((const float4*)g_lin)[i];
    float4 r;
    float t;
    t = (v.x + bconv[c4+0] - g_mshift[c4+0]) * g_rsig[c4+0] + gnb[c4+0] + l.x;
    r.x = t > 0.f ? t : expm1f(t);
    t = (v.y + bconv[c4+1] - g_mshift[c4+1]) * g_rsig[c4+1] + gnb[c4+1] + l.y;
    r.y = t > 0.f ? t : expm1f(t);
    t = (v.z + bconv[c4+2] - g_mshift[c4+2]) * g_rsig[c4+2] + gnb[c4+2] + l.z;
    r.z = t > 0.f ? t : expm1f(t);
    t = (v.w + bconv[c4+3] - g_mshift[c4+3]) * g_rsig[c4+3] + gnb[c4+3] + l.w;
    r.w = t > 0.f ? t : expm1f(t);
    ((float4*)g_emb)[i] = r;
}

// ---------------- final combine + log_softmax ----------------
__global__ void k_final(const float* __restrict__ fbconv, float* __restrict__ out) {
    int n = blockIdx.x * blockDim.x + threadIdx.x;
    if (n >= NN) return;
    float t[OUTC];
    #pragma unroll
    for (int o = 0; o < OUTC; ++o) {
        float s = 0.f;
        #pragma unroll
        for (int h = 0; h < HH; ++h) s += g_fagg[(size_t)n * FD + h * OUTC + o];
        t[o] = 0.25f * s + fbconv[o] + g_flin[(size_t)n * OUTC + o];
    }
    float m = t[0];
    #pragma unroll
    for (int o = 1; o < OUTC; ++o) m = fmaxf(m, t[o]);
    float lse = 0.f;
    #pragma unroll
    for (int o = 0; o < OUTC; ++o) lse += expf(t[o] - m);
    lse = logf(lse);
    #pragma unroll
    for (int o = 0; o < OUTC; ++o) out[(size_t)n * OUTC + o] = t[o] - m - lse;
}

// ---------------- host ----------------
extern "C" void kernel_launch(void* const* d_in, const int* in_sizes, int n_in,
                              void* d_out, int out_size) {
    const float* x      = (const float*)d_in[0];
    const int*   ei     = (const int*)d_in[1];
    const float* Wl     = (const float*)d_in[2];
    const float* Wr     = (const float*)d_in[3];
    const float* att    = (const float*)d_in[4];
    const float* bconv  = (const float*)d_in[5];
    const float* Wlin   = (const float*)d_in[6];
    const float* blin   = (const float*)d_in[7];
    const float* gnw    = (const float*)d_in[8];
    const float* gnb    = (const float*)d_in[9];
    const float* gnms   = (const float*)d_in[10];
    const float* fWl    = (const float*)d_in[11];
    const float* fWr    = (const float*)d_in[12];
    const float* fatt   = (const float*)d_in[13];
    const float* fbconv = (const float*)d_in[14];
    const float* fWlin  = (const float*)d_in[15];
    const float* fblin  = (const float*)d_in[16];
    float* out = (float*)d_out;

    cudaFuncSetAttribute(k_mma3, cudaFuncAttributeMaxDynamicSharedMemorySize,
                         MMA_SMEM);

    float *p_emb, *p_xl, *p_xr, *p_lin, *p_fxl, *p_fxr, *p_flin, *p_colstat;
    int *p_deg, *p_pos;
    cudaGetSymbolAddress((void**)&p_emb,  g_emb);
    cudaGetSymbolAddress((void**)&p_xl,   g_xl);
    cudaGetSymbolAddress((void**)&p_xr,   g_xr);
    cudaGetSymbolAddress((void**)&p_lin,  g_lin);
    cudaGetSymbolAddress((void**)&p_fxl,  g_fxl);
    cudaGetSymbolAddress((void**)&p_fxr,  g_fxr);
    cudaGetSymbolAddress((void**)&p_flin, g_flin);
    cudaGetSymbolAddress((void**)&p_colstat, g_colstat);
    cudaGetSymbolAddress((void**)&p_deg,  g_deg);
    cudaGetSymbolAddress((void**)&p_pos,  g_pos);

    const int EH_BLOCKS = (EE * HH + 255) / 256;
    const int E_BLOCKS  = (EE + 255) / 256;

    // ---- CSR build ----
    cudaMemsetAsync(p_deg, 0, NN * sizeof(int));
    cudaMemsetAsync(p_pos, 0, NN * sizeof(int));
    k_hist<<<E_BLOCKS, 256>>>(ei);
    k_scan<<<1, 1024>>>();
    k_scatter<<<E_BLOCKS, 256>>>(ei);

    const float* embp = x;
    for (int i = 0; i < 2; ++i) {
        const size_t wo = (size_t)i * DD * DD;
        dim3 grid(6, (NN + 127) / 128);
        k_mma3<<<grid, 256, MMA_SMEM>>>(embp, Wl + wo, Wr + wo, Wlin + wo,
                                        blin + i * DD, p_xl, p_xr, p_lin, NN);
        k_edge_score64<<<EH_BLOCKS, 256>>>((const float4*)p_xl, (const float4*)p_xr,
                                           att + i * HH * CC);
        k_softmax_csr<<<(NN + 7) / 8, 256>>>();
        k_agg_csr<<<NN / 4, 256>>>((const float4*)p_xl);
        cudaMemsetAsync(p_colstat, 0, 2 * DD * sizeof(float));
        k_colstats<<<256, 256>>>(bconv + i * DD);
        k_finstats<<<1, 256>>>(gnw + i * DD, gnms + i * DD);
        k_fuse<<<(NN * (DD / 4) + 255) / 256, 256>>>(bconv + i * DD, gnb + i * DD);
        embp = p_emb;
    }

    // final layer (merged small GEMMs)
    k_gemm_f3<<<(NN + 127) / 128, 192>>>(p_emb, fWl, fWr, fWlin, fblin,
                                         p_fxl, p_fxr, p_flin, NN);
    k_edge_score_f<<<EH_BLOCKS, 256>>>(p_fxl, p_fxr, fatt);
    k_softmax_csr<<<(NN + 7) / 8, 256>>>();
    k_agg_csr_f<<<NN / 8, 256>>>();
    k_final<<<(NN + 255) / 256, 256>>>(fbconv, out);
}

// round 10
// speedup vs baseline: 2.5082x; 1.5757x over previous
#include <cuda_runtime.h>
#include <cuda_bf16.h>
#include <math.h>
#include <stdint.h>

#define NN 50000
#define EE 800000
#define DD 256
#define HH 4
#define CC 64
#define OUTC 5
#define FD (HH*OUTC)   // 20
#define NEG 0.2f
#define GN_EPS 1e-5f
#define SM_EPS 1e-16f

// ---------------- scratch (device globals, no allocation) ----------------
__device__ float g_emb[NN*DD];
__device__ float g_xl [NN*DD];
__device__ float g_xr [NN*DD];
__device__ float g_lin[NN*DD];
__device__ float g_agg[NN*DD];
__device__ float g_score[EE*HH];
__device__ float g_colstat[2*DD];
__device__ float g_mshift[DD];
__device__ float g_rsig  [DD];
__device__ float g_fxl [NN*FD];
__device__ float g_fxr [NN*FD];
__device__ float g_fagg[NN*FD];
__device__ float g_flin[NN*OUTC];
// CSR by destination
__device__ int g_deg[NN];
__device__ int g_off[NN+1];
__device__ int g_pos[NN];
__device__ int g_esrc[EE];
__device__ int g_edst[EE];

#define MMA_BF16(c, a, b)                                                     \
    asm volatile("mma.sync.aligned.m16n8k16.row.col.f32.bf16.bf16.f32 "       \
                 "{%0,%1,%2,%3}, {%4,%5,%6,%7}, {%8,%9}, {%0,%1,%2,%3};"      \
                 : "+f"((c)[0]), "+f"((c)[1]), "+f"((c)[2]), "+f"((c)[3])     \
                 : "r"((a)[0]), "r"((a)[1]), "r"((a)[2]), "r"((a)[3]),        \
                   "r"((b)[0]), "r"((b)[1]))

// split two floats into packed bf16x2 hi and lo (k-even in low half)
static __device__ __forceinline__ void split2(float a, float b,
                                              uint32_t& hi, uint32_t& lo) {
    __nv_bfloat16 ha = __float2bfloat16(a), hb = __float2bfloat16(b);
    float ra = a - __bfloat162float(ha);
    float rb = b - __bfloat162float(hb);
    __nv_bfloat16 la = __float2bfloat16(ra), lb = __float2bfloat16(rb);
    hi = ((uint32_t)__bfloat16_as_ushort(hb) << 16) | __bfloat16_as_ushort(ha);
    lo = ((uint32_t)__bfloat16_as_ushort(lb) << 16) | __bfloat16_as_ushort(la);
}

// ---------------- tensor-core GEMM: 3 outputs in one launch ---------------
// 3xBF16 compensation, m16n8k16, double-buffered. Stride 136 (conflict-free).
#define PADW 136
#define CHU (8*PADW)
#define MMA_SMEM (8*CHU*4)

__global__ __launch_bounds__(256, 2)
void k_mma3(const float* __restrict__ A,
            const float* __restrict__ B0, const float* __restrict__ B1,
            const float* __restrict__ B2, const float* __restrict__ bias2,
            float* __restrict__ C0, float* __restrict__ C1,
            float* __restrict__ C2, int M) {
    extern __shared__ uint32_t smu[];
    uint32_t* AhB = smu;
    uint32_t* AlB = smu + 2 * CHU;
    uint32_t* BhB = smu + 4 * CHU;
    uint32_t* BlB = smu + 6 * CHU;

    const int mat = blockIdx.x >> 1;
    const float* __restrict__ B = (mat == 0) ? B0 : (mat == 1) ? B1 : B2;
    float* __restrict__ C = (mat == 0) ? C0 : (mat == 1) ? C1 : C2;
    const float* bias = (mat == 2) ? bias2 : nullptr;

    const int tid = threadIdx.x;
    const int lane = tid & 31, wid = tid >> 5;
    const int warpRow = wid >> 2, warpCol = wid & 3;
    const int rowBase = blockIdx.y * 128;
    const int colBase = (blockIdx.x & 1) * 128;

    float c[4][4][4];
    #pragma unroll
    for (int mt = 0; mt < 4; ++mt)
        #pragma unroll
        for (int nt = 0; nt < 4; ++nt)
            #pragma unroll
            for (int j = 0; j < 4; ++j) c[mt][nt][j] = 0.f;

    const int aRow = tid >> 1;
    const int aHalf = tid & 1;
    const bool aOk = (rowBase + aRow) < M;
    const int kpB = tid >> 5, qB = tid & 31;

    const int gid = lane >> 2;
    const int tig = lane & 3;

    float4 av0, av1, bv0, bv1;
    av0 = aOk ? *(const float4*)(A + (size_t)(rowBase + aRow) * 256 + aHalf * 8)
              : make_float4(0.f, 0.f, 0.f, 0.f);
    av1 = aOk ? *(const float4*)(A + (size_t)(rowBase + aRow) * 256 + aHalf * 8 + 4)
              : make_float4(0.f, 0.f, 0.f, 0.f);
    bv0 = *(const float4*)(B + (size_t)(2 * kpB) * 256 + colBase + qB * 4);
    bv1 = *(const float4*)(B + (size_t)(2 * kpB + 1) * 256 + colBase + qB * 4);
    {
        uint32_t h, l;
        int kb = aHalf * 4;
        split2(av0.x, av0.y, h, l); AhB[(kb+0)*PADW + aRow] = h; AlB[(kb+0)*PADW + aRow] = l;
        split2(av0.z, av0.w, h, l); AhB[(kb+1)*PADW + aRow] = h; AlB[(kb+1)*PADW + aRow] = l;
        split2(av1.x, av1.y, h, l); AhB[(kb+2)*PADW + aRow] = h; AlB[(kb+2)*PADW + aRow] = l;
        split2(av1.z, av1.w, h, l); AhB[(kb+3)*PADW + aRow] = h; AlB[(kb+3)*PADW + aRow] = l;
        split2(bv0.x, bv1.x, h, l); BhB[kpB*PADW + qB*4+0] = h; BlB[kpB*PADW + qB*4+0] = l;
        split2(bv0.y, bv1.y, h, l); BhB[kpB*PADW + qB*4+1] = h; BlB[kpB*PADW + qB*4+1] = l;
        split2(bv0.z, bv1.z, h, l); BhB[kpB*PADW + qB*4+2] = h; BlB[kpB*PADW + qB*4+2] = l;
        split2(bv0.w, bv1.w, h, l); BhB[kpB*PADW + qB*4+3] = h; BlB[kpB*PADW + qB*4+3] = l;
    }
    __syncthreads();

    for (int ch = 0; ch < 16; ++ch) {
        const int cur = ch & 1, nxt = cur ^ 1;
        if (ch < 15) {
            const int kg = (ch + 1) * 16;
            av0 = aOk ? *(const float4*)(A + (size_t)(rowBase + aRow) * 256 + kg + aHalf * 8)
                      : make_float4(0.f, 0.f, 0.f, 0.f);
            av1 = aOk ? *(const float4*)(A + (size_t)(rowBase + aRow) * 256 + kg + aHalf * 8 + 4)
                      : make_float4(0.f, 0.f, 0.f, 0.f);
            bv0 = *(const float4*)(B + (size_t)(kg + 2 * kpB) * 256 + colBase + qB * 4);
            bv1 = *(const float4*)(B + (size_t)(kg + 2 * kpB + 1) * 256 + colBase + qB * 4);
        }
        const uint32_t* Ah = AhB + cur * CHU;
        const uint32_t* Al = AlB + cur * CHU;
        const uint32_t* Bh = BhB + cur * CHU;
        const uint32_t* Bl = BlB + cur * CHU;

        uint32_t bhf[4][2], blf[4][2];
        #pragma unroll
        for (int nt = 0; nt < 4; ++nt) {
            int n = warpCol * 32 + nt * 8 + gid;
            bhf[nt][0] = Bh[tig*PADW + n];
            bhf[nt][1] = Bh[(tig+4)*PADW + n];
            blf[nt][0] = Bl[tig*PADW + n];
            blf[nt][1] = Bl[(tig+4)*PADW + n];
        }
        #pragma unroll
        for (int mt = 0; mt < 4; ++mt) {
            int m = warpRow * 64 + mt * 16 + gid;
            uint32_t ahi[4], alo[4];
            ahi[0] = Ah[tig*PADW + m];
            ahi[1] = Ah[tig*PADW + m + 8];
            ahi[2] = Ah[(tig+4)*PADW + m];
            ahi[3] = Ah[(tig+4)*PADW + m + 8];
            alo[0] = Al[tig*PADW + m];
            alo[1] = Al[tig*PADW + m + 8];
            alo[2] = Al[(tig+4)*PADW + m];
            alo[3] = Al[(tig+4)*PADW + m + 8];
            #pragma unroll
            for (int nt = 0; nt < 4; ++nt) {
                MMA_BF16(c[mt][nt], ahi, bhf[nt]);
                MMA_BF16(c[mt][nt], ahi, blf[nt]);
                MMA_BF16(c[mt][nt], alo, bhf[nt]);
            }
        }
        if (ch < 15) {
            uint32_t* Ahn = AhB + nxt * CHU;
            uint32_t* Aln = AlB + nxt * CHU;
            uint32_t* Bhn = BhB + nxt * CHU;
            uint32_t* Bln = BlB + nxt * CHU;
            uint32_t h, l;
            int kb = aHalf * 4;
            split2(av0.x, av0.y, h, l); Ahn[(kb+0)*PADW + aRow] = h; Aln[(kb+0)*PADW + aRow] = l;
            split2(av0.z, av0.w, h, l); Ahn[(kb+1)*PADW + aRow] = h; Aln[(kb+1)*PADW + aRow] = l;
            split2(av1.x, av1.y, h, l); Ahn[(kb+2)*PADW + aRow] = h; Aln[(kb+2)*PADW + aRow] = l;
            split2(av1.z, av1.w, h, l); Ahn[(kb+3)*PADW + aRow] = h; Aln[(kb+3)*PADW + aRow] = l;
            split2(bv0.x, bv1.x, h, l); Bhn[kpB*PADW + qB*4+0] = h; Bln[kpB*PADW + qB*4+0] = l;
            split2(bv0.y, bv1.y, h, l); Bhn[kpB*PADW + qB*4+1] = h; Bln[kpB*PADW + qB*4+1] = l;
            split2(bv0.z, bv1.z, h, l); Bhn[kpB*PADW + qB*4+2] = h; Bln[kpB*PADW + qB*4+2] = l;
            split2(bv0.w, bv1.w, h, l); Bhn[kpB*PADW + qB*4+3] = h; Bln[kpB*PADW + qB*4+3] = l;
            __syncthreads();
        }
    }

    #pragma unroll
    for (int mt = 0; mt < 4; ++mt) {
        int row = rowBase + warpRow * 64 + mt * 16 + gid;
        #pragma unroll
        for (int nt = 0; nt < 4; ++nt) {
            int col = colBase + warpCol * 32 + nt * 8 + tig * 2;
            float b0 = bias ? bias[col] : 0.f;
            float b1 = bias ? bias[col + 1] : 0.f;
            if (row < M) {
                float2 o = make_float2(c[mt][nt][0] + b0, c[mt][nt][1] + b1);
                *(float2*)(C + (size_t)row * 256 + col) = o;
            }
            if (row + 8 < M) {
                float2 o = make_float2(c[mt][nt][2] + b0, c[mt][nt][3] + b1);
                *(float2*)(C + (size_t)(row + 8) * 256 + col) = o;
            }
        }
    }
}

// ---- fused GATv2 edge phase: warp per node, online softmax + aggregate ---
// lane l owns channels [8l, 8l+8); head = l>>3; 8-lane butterfly for scores.
__global__ __launch_bounds__(256)
void k_gat_fused(const float4* __restrict__ xl, const float4* __restrict__ xr,
                 const float* __restrict__ att) {
    int node = blockIdx.x * 8 + (threadIdx.x >> 5);
    int lane = threadIdx.x & 31;

    // per-lane statics: xr row slice + att slice
    float4 xr0 = xr[(size_t)node * 64 + lane * 2];
    float4 xr1 = xr[(size_t)node * 64 + lane * 2 + 1];
    float4 at0 = ((const float4*)att)[lane * 2];
    float4 at1 = ((const float4*)att)[lane * 2 + 1];

    float m = -1e30f, den = 0.f;
    float4 acc0 = make_float4(0.f, 0.f, 0.f, 0.f);
    float4 acc1 = make_float4(0.f, 0.f, 0.f, 0.f);

    int beg = g_off[node], end = g_off[node + 1];
    for (int j = beg; j < end; ++j) {
        int src = g_esrc[j];
        float4 a0 = xl[(size_t)src * 64 + lane * 2];
        float4 a1 = xl[(size_t)src * 64 + lane * 2 + 1];
        float v, p = 0.f;
        v = a0.x + xr0.x; v = v > 0.f ? v : NEG * v; p += at0.x * v;
        v = a0.y + xr0.y; v = v > 0.f ? v : NEG * v; p += at0.y * v;
        v = a0.z + xr0.z; v = v > 0.f ? v : NEG * v; p += at0.z * v;
        v = a0.w + xr0.w; v = v > 0.f ? v : NEG * v; p += at0.w * v;
        v = a1.x + xr1.x; v = v > 0.f ? v : NEG * v; p += at1.x * v;
        v = a1.y + xr1.y; v = v > 0.f ? v : NEG * v; p += at1.y * v;
        v = a1.z + xr1.z; v = v > 0.f ? v : NEG * v; p += at1.z * v;
        v = a1.w + xr1.w; v = v > 0.f ? v : NEG * v; p += at1.w * v;
        p += __shfl_xor_sync(~0u, p, 1);
        p += __shfl_xor_sync(~0u, p, 2);
        p += __shfl_xor_sync(~0u, p, 4);     // head score, uniform in 8-group

        if (p <= m) {
            float w = __expf(p - m);
            den += w;
            acc0.x += w * a0.x; acc0.y += w * a0.y;
            acc0.z += w * a0.z; acc0.w += w * a0.w;
            acc1.x += w * a1.x; acc1.y += w * a1.y;
            acc1.z += w * a1.z; acc1.w += w * a1.w;
        } else {
            float sc = __expf(m - p);
            den = den * sc + 1.f;
            acc0.x = acc0.x * sc + a0.x; acc0.y = acc0.y * sc + a0.y;
            acc0.z = acc0.z * sc + a0.z; acc0.w = acc0.w * sc + a0.w;
            acc1.x = acc1.x * sc + a1.x; acc1.y = acc1.y * sc + a1.y;
            acc1.z = acc1.z * sc + a1.z; acc1.w = acc1.w * sc + a1.w;
            m = p;
        }
    }
    float inv = 1.f / (den + SM_EPS);
    acc0.x *= inv; acc0.y *= inv; acc0.z *= inv; acc0.w *= inv;
    acc1.x *= inv; acc1.y *= inv; acc1.z *= inv; acc1.w *= inv;
    ((float4*)g_agg)[(size_t)node * 64 + lane * 2] = acc0;
    ((float4*)g_agg)[(size_t)node * 64 + lane * 2 + 1] = acc1;
}

// ------- merged final GEMMs: fxl[.,20], fxr[.,20], flin[.,5] in one pass ---
__global__ __launch_bounds__(192)
void k_gemm_f3(const float* __restrict__ A,
               const float* __restrict__ B0, const float* __restrict__ B1,
               const float* __restrict__ B2, const float* __restrict__ bias2,
               float* __restrict__ C0, float* __restrict__ C1,
               float* __restrict__ C2, int M) {
    __shared__ float As[16][129];
    __shared__ float Bs[16][48];
    const int tid = threadIdx.x;
    const int tx = tid % 48, ty = tid / 48;
    const int rowBase = blockIdx.x * 128;

    float acc[32];
    #pragma unroll
    for (int r = 0; r < 32; ++r) acc[r] = 0.f;

    for (int ch = 0; ch < 16; ++ch) {
        for (int i = tid; i < 2048; i += 192) {
            int row = i >> 4, k = i & 15;
            int gr = rowBase + row;
            As[k][row] = (gr < M) ? A[(size_t)gr * 256 + ch * 16 + k] : 0.f;
        }
        for (int i = tid; i < 768; i += 192) {
            int k = i / 48, cc = i % 48;
            float v = 0.f;
            int gk = ch * 16 + k;
            if (cc < FD)            v = B0[(size_t)gk * FD + cc];
            else if (cc < 2 * FD)   v = B1[(size_t)gk * FD + (cc - FD)];
            else if (cc < 2 * FD + OUTC) v = B2[(size_t)gk * OUTC + (cc - 2 * FD)];
            Bs[k][cc] = v;
        }
        __syncthreads();
        #pragma unroll
        for (int k = 0; k < 16; ++k) {
            float b = Bs[k][tx];
            #pragma unroll
            for (int r = 0; r < 32; ++r) acc[r] += As[k][ty * 32 + r] * b;
        }
        __syncthreads();
    }

    #pragma unroll
    for (int r = 0; r < 32; ++r) {
        int row = rowBase + ty * 32 + r;
        if (row >= M) break;
        if (tx < FD) {
            C0[(size_t)row * FD + tx] = acc[r];
        } else if (tx < 2 * FD) {
            C1[(size_t)row * FD + (tx - FD)] = acc[r];
        } else if (tx < 2 * FD + OUTC) {
            C2[(size_t)row * OUTC + (tx - 2 * FD)] = acc[r] + bias2[tx - 2 * FD];
        }
    }
}

// ---------------- CSR build ----------------
__global__ void k_hist(const int* __restrict__ ei) {
    int e = blockIdx.x * blockDim.x + threadIdx.x;
    if (e < EE) atomicAdd(&g_deg[ei[EE + e]], 1);
}

__global__ void k_scan() {
    __shared__ int wsum[32];
    const int CH = 49;
    int t = threadIdx.x;
    int base = t * CH;
    int s = 0;
    for (int i = 0; i < CH; ++i) {
        int idx = base + i;
        if (idx < NN) s += g_deg[idx];
    }
    int lane = t & 31, wid = t >> 5;
    int v = s;
    #pragma unroll
    for (int d = 1; d < 32; d <<= 1) {
        int n = __shfl_up_sync(~0u, v, d);
        if (lane >= d) v += n;
    }
    if (lane == 31) wsum[wid] = v;
    __syncthreads();
    if (wid == 0) {
        int wv = wsum[lane];
        #pragma unroll
        for (int d = 1; d < 32; d <<= 1) {
            int n = __shfl_up_sync(~0u, wv, d);
            if (lane >= d) wv += n;
        }
        wsum[lane] = wv;
    }
    __syncthreads();
    int pre = (v - s) + (wid > 0 ? wsum[wid - 1] : 0);
    for (int i = 0; i < CH; ++i) {
        int idx = base + i;
        if (idx < NN) { g_off[idx] = pre; pre += g_deg[idx]; }
    }
    if (t == 1023) g_off[NN] = pre;
}

__global__ void k_scatter(const int* __restrict__ ei) {
    int e = blockIdx.x * blockDim.x + threadIdx.x;
    if (e >= EE) return;
    int src = ei[e], dst = ei[EE + e];
    int p = atomicAdd(&g_pos[dst], 1);
    int slot = g_off[dst] + p;
    g_esrc[slot] = src;
    g_edst[slot] = dst;
}

// ---------------- final-layer edge scoring ----------------
__global__ void k_edge_score_f(const float* __restrict__ xl,
                               const float* __restrict__ xr,
                               const float* __restrict__ att) {
    int idx = blockIdx.x * blockDim.x + threadIdx.x;
    if (idx >= EE * HH) return;
    int j = idx >> 2, h = idx & 3;
    int src = g_esrc[j], dst = g_edst[j];
    const float* pl = xl + (size_t)src * FD + h * OUTC;
    const float* pr = xr + (size_t)dst * FD + h * OUTC;
    const float* pa = att + h * OUTC;
    float s = 0.f;
    #pragma unroll
    for (int c = 0; c < OUTC; ++c) {
        float v = pl[c] + pr[c];
        v = v > 0.f ? v : NEG * v;
        s += pa[c] * v;
    }
    g_score[idx] = s;
}

// ---------------- segment softmax (final layer) ----------------
__global__ void k_softmax_csr() {
    int w = (blockIdx.x * blockDim.x + threadIdx.x) >> 5;
    if (w >= NN) return;
    int lane = threadIdx.x & 31;
    int beg = g_off[w], end = g_off[w + 1];
    int h = lane & 3;
    int j0 = beg + (lane >> 2);

    float m = -1e30f;
    for (int j = j0; j < end; j += 8) m = fmaxf(m, g_score[j * 4 + h]);
    #pragma unroll
    for (int d = 4; d < 32; d <<= 1) m = fmaxf(m, __shfl_xor_sync(~0u, m, d));

    float den = 0.f;
    for (int j = j0; j < end; j += 8) den += __expf(g_score[j * 4 + h] - m);
    #pragma unroll
    for (int d = 4; d < 32; d <<= 1) den += __shfl_xor_sync(~0u, den, d);
    float inv = 1.f / (den + SM_EPS);

    for (int j = j0; j < end; j += 8)
        g_score[j * 4 + h] = __expf(g_score[j * 4 + h] - m) * inv;
}

__global__ void k_agg_csr_f() {
    int node = blockIdx.x * 8 + (threadIdx.x >> 5);
    int t = threadIdx.x & 31;
    if (t >= FD) return;
    int h = t / OUTC;
    int beg = g_off[node], end = g_off[node + 1];
    float acc = 0.f;
    for (int j = beg; j < end; ++j) {
        int src = g_esrc[j];
        acc += g_score[j * 4 + h] * g_fxl[(size_t)src * FD + t];
    }
    g_fagg[(size_t)node * FD + t] = acc;
}

// ---------------- GraphNorm ----------------
__global__ void k_colstats(const float* __restrict__ bconv) {
    int t = threadIdx.x;
    float bc = bconv[t];
    float s = 0.f, q = 0.f;
    for (int r = blockIdx.x; r < NN; r += gridDim.x) {
        float v = g_agg[(size_t)r * DD + t] + bc;
        s += v; q += v * v;
    }
    atomicAdd(&g_colstat[t], s);
    atomicAdd(&g_colstat[DD + t], q);
}

__global__ void k_finstats(const float* __restrict__ gnw, const float* __restrict__ gnms) {
    int t = threadIdx.x;
    float mean = g_colstat[t] * (1.f / NN);
    float ms = mean * gnms[t];
    float var = g_colstat[DD + t] * (1.f / NN) - 2.f * ms * mean + ms * ms;
    g_mshift[t] = ms;
    g_rsig[t] = gnw[t] * rsqrtf(var + GN_EPS);
}

__global__ void k_fuse(const float* __restrict__ bconv, const float* __restrict__ gnb) {
    int i = blockIdx.x * blockDim.x + threadIdx.x;
    if (i >= NN * (DD / 4)) return;
    int c4 = (i & 63) * 4;
    float4 v = ((const float4*)g_agg)[i];
    float4 l = ((const float4*)g_lin)[i];
    float4 r;
    float t;
    t = (v.x + bconv[c4+0] - g_mshift[c4+0]) * g_rsig[c4+0] + gnb[c4+0] + l.x;
    r.x = t > 0.f ? t : expm1f(t);
    t = (v.y + bconv[c4+1] - g_mshift[c4+1]) * g_rsig[c4+1] + gnb[c4+1] + l.y;
    r.y = t > 0.f ? t : expm1f(t);
    t = (v.z + bconv[c4+2] - g_mshift[c4+2]) * g_rsig[c4+2] + gnb[c4+2] + l.z;
    r.z = t > 0.f ? t : expm1f(t);
    t = (v.w + bconv[c4+3] - g_mshift[c4+3]) * g_rsig[c4+3] + gnb[c4+3] + l.w;
    r.w = t > 0.f ? t : expm1f(t);
    ((float4*)g_emb)[i] = r;
}

// ---------------- final combine + log_softmax ----------------
__global__ void k_final(const float* __restrict__ fbconv, float* __restrict__ out) {
    int n = blockIdx.x * blockDim.x + threadIdx.x;
    if (n >= NN) return;
    float t[OUTC];
    #pragma unroll
    for (int o = 0; o < OUTC; ++o) {
        float s = 0.f;
        #pragma unroll
        for (int h = 0; h < HH; ++h) s += g_fagg[(size_t)n * FD + h * OUTC + o];
        t[o] = 0.25f * s + fbconv[o] + g_flin[(size_t)n * OUTC + o];
    }
    float m = t[0];
    #pragma unroll
    for (int o = 1; o < OUTC; ++o) m = fmaxf(m, t[o]);
    float lse = 0.f;
    #pragma unroll
    for (int o = 0; o < OUTC; ++o) lse += expf(t[o] - m);
    lse = logf(lse);
    #pragma unroll
    for (int o = 0; o < OUTC; ++o) out[(size_t)n * OUTC + o] = t[o] - m - lse;
}

// ---------------- host ----------------
extern "C" void kernel_launch(void* const* d_in, const int* in_sizes, int n_in,
                              void* d_out, int out_size) {
    const float* x      = (const float*)d_in[0];
    const int*   ei     = (const int*)d_in[1];
    const float* Wl     = (const float*)d_in[2];
    const float* Wr     = (const float*)d_in[3];
    const float* att    = (const float*)d_in[4];
    const float* bconv  = (const float*)d_in[5];
    const float* Wlin   = (const float*)d_in[6];
    const float* blin   = (const float*)d_in[7];
    const float* gnw    = (const float*)d_in[8];
    const float* gnb    = (const float*)d_in[9];
    const float* gnms   = (const float*)d_in[10];
    const float* fWl    = (const float*)d_in[11];
    const float* fWr    = (const float*)d_in[12];
    const float* fatt   = (const float*)d_in[13];
    const float* fbconv = (const float*)d_in[14];
    const float* fWlin  = (const float*)d_in[15];
    const float* fblin  = (const float*)d_in[16];
    float* out = (float*)d_out;

    cudaFuncSetAttribute(k_mma3, cudaFuncAttributeMaxDynamicSharedMemorySize,
                         MMA_SMEM);

    float *p_emb, *p_xl, *p_xr, *p_lin, *p_fxl, *p_fxr, *p_flin, *p_colstat;
    int *p_deg, *p_pos;
    cudaGetSymbolAddress((void**)&p_emb,  g_emb);
    cudaGetSymbolAddress((void**)&p_xl,   g_xl);
    cudaGetSymbolAddress((void**)&p_xr,   g_xr);
    cudaGetSymbolAddress((void**)&p_lin,  g_lin);
    cudaGetSymbolAddress((void**)&p_fxl,  g_fxl);
    cudaGetSymbolAddress((void**)&p_fxr,  g_fxr);
    cudaGetSymbolAddress((void**)&p_flin, g_flin);
    cudaGetSymbolAddress((void**)&p_colstat, g_colstat);
    cudaGetSymbolAddress((void**)&p_deg,  g_deg);
    cudaGetSymbolAddress((void**)&p_pos,  g_pos);

    const int EH_BLOCKS = (EE * HH + 255) / 256;
    const int E_BLOCKS  = (EE + 255) / 256;

    // ---- CSR build ----
    cudaMemsetAsync(p_deg, 0, NN * sizeof(int));
    cudaMemsetAsync(p_pos, 0, NN * sizeof(int));
    k_hist<<<E_BLOCKS, 256>>>(ei);
    k_scan<<<1, 1024>>>();
    k_scatter<<<E_BLOCKS, 256>>>(ei);

    const float* embp = x;
    for (int i = 0; i < 2; ++i) {
        const size_t wo = (size_t)i * DD * DD;
        dim3 grid(6, (NN + 127) / 128);
        k_mma3<<<grid, 256, MMA_SMEM>>>(embp, Wl + wo, Wr + wo, Wlin + wo,
                                        blin + i * DD, p_xl, p_xr, p_lin, NN);
        k_gat_fused<<<(NN + 7) / 8, 256>>>((const float4*)p_xl, (const float4*)p_xr,
                                           att + i * HH * CC);
        cudaMemsetAsync(p_colstat, 0, 2 * DD * sizeof(float));
        k_colstats<<<256, 256>>>(bconv + i * DD);
        k_finstats<<<1, 256>>>(gnw + i * DD, gnms + i * DD);
        k_fuse<<<(NN * (DD / 4) + 255) / 256, 256>>>(bconv + i * DD, gnb + i * DD);
        embp = p_emb;
    }

    // final layer
    k_gemm_f3<<<(NN + 127) / 128, 192>>>(p_emb, fWl, fWr, fWlin, fblin,
                                         p_fxl, p_fxr, p_flin, NN);
    k_edge_score_f<<<EH_BLOCKS, 256>>>(p_fxl, p_fxr, fatt);
    k_softmax_csr<<<(NN + 7) / 8, 256>>>();
    k_agg_csr_f<<<NN / 8, 256>>>();
    k_final<<<(NN + 255) / 256, 256>>>(fbconv, out);
}

// round 11
// speedup vs baseline: 2.6962x; 1.0750x over previous
#include <cuda_runtime.h>
#include <cuda_bf16.h>
#include <math.h>
#include <stdint.h>

#define NN 50000
#define EE 800000
#define DD 256
#define HH 4
#define CC 64
#define OUTC 5
#define FD (HH*OUTC)   // 20
#define NEG 0.2f
#define GN_EPS 1e-5f
#define SM_EPS 1e-16f

// ---------------- scratch (device globals, no allocation) ----------------
__device__ float g_emb[NN*DD];
__device__ float g_xl [NN*DD];
__device__ float g_xr [NN*DD];
__device__ float g_lin[NN*DD];
__device__ float g_agg[NN*DD];
__device__ float g_colstat[2*DD];
__device__ float g_mshift[DD];
__device__ float g_rsig  [DD];
__device__ float g_fxl [NN*FD];
__device__ float g_fxr [NN*FD];
__device__ float g_fagg[NN*FD];
__device__ float g_flin[NN*OUTC];
// CSR by destination
__device__ int g_deg[NN];
__device__ int g_off[NN+1];
__device__ int g_pos[NN];
__device__ int g_esrc[EE];

#define MMA_BF16(c, a, b)                                                     \
    asm volatile("mma.sync.aligned.m16n8k16.row.col.f32.bf16.bf16.f32 "       \
                 "{%0,%1,%2,%3}, {%4,%5,%6,%7}, {%8,%9}, {%0,%1,%2,%3};"      \
                 : "+f"((c)[0]), "+f"((c)[1]), "+f"((c)[2]), "+f"((c)[3])     \
                 : "r"((a)[0]), "r"((a)[1]), "r"((a)[2]), "r"((a)[3]),        \
                   "r"((b)[0]), "r"((b)[1]))

// split two floats into packed bf16x2 hi and lo (k-even in low half)
static __device__ __forceinline__ void split2(float a, float b,
                                              uint32_t& hi, uint32_t& lo) {
    __nv_bfloat16 ha = __float2bfloat16(a), hb = __float2bfloat16(b);
    float ra = a - __bfloat162float(ha);
    float rb = b - __bfloat162float(hb);
    __nv_bfloat16 la = __float2bfloat16(ra), lb = __float2bfloat16(rb);
    hi = ((uint32_t)__bfloat16_as_ushort(hb) << 16) | __bfloat16_as_ushort(ha);
    lo = ((uint32_t)__bfloat16_as_ushort(lb) << 16) | __bfloat16_as_ushort(la);
}

// ---------------- tensor-core GEMM: 3 outputs in one launch ---------------
// 3xBF16 compensation, m16n8k16, double-buffered. Stride 136 (conflict-free).
#define PADW 136
#define CHU (8*PADW)
#define MMA_SMEM (8*CHU*4)

__global__ __launch_bounds__(256, 2)
void k_mma3(const float* __restrict__ A,
            const float* __restrict__ B0, const float* __restrict__ B1,
            const float* __restrict__ B2, const float* __restrict__ bias2,
            float* __restrict__ C0, float* __restrict__ C1,
            float* __restrict__ C2, int M) {
    extern __shared__ uint32_t smu[];
    uint32_t* AhB = smu;
    uint32_t* AlB = smu + 2 * CHU;
    uint32_t* BhB = smu + 4 * CHU;
    uint32_t* BlB = smu + 6 * CHU;

    const int mat = blockIdx.x >> 1;
    const float* __restrict__ B = (mat == 0) ? B0 : (mat == 1) ? B1 : B2;
    float* __restrict__ C = (mat == 0) ? C0 : (mat == 1) ? C1 : C2;
    const float* bias = (mat == 2) ? bias2 : nullptr;

    const int tid = threadIdx.x;
    const int lane = tid & 31, wid = tid >> 5;
    const int warpRow = wid >> 2, warpCol = wid & 3;
    const int rowBase = blockIdx.y * 128;
    const int colBase = (blockIdx.x & 1) * 128;

    float c[4][4][4];
    #pragma unroll
    for (int mt = 0; mt < 4; ++mt)
        #pragma unroll
        for (int nt = 0; nt < 4; ++nt)
            #pragma unroll
            for (int j = 0; j < 4; ++j) c[mt][nt][j] = 0.f;

    const int aRow = tid >> 1;
    const int aHalf = tid & 1;
    const bool aOk = (rowBase + aRow) < M;
    const int kpB = tid >> 5, qB = tid & 31;

    const int gid = lane >> 2;
    const int tig = lane & 3;

    float4 av0, av1, bv0, bv1;
    av0 = aOk ? *(const float4*)(A + (size_t)(rowBase + aRow) * 256 + aHalf * 8)
              : make_float4(0.f, 0.f, 0.f, 0.f);
    av1 = aOk ? *(const float4*)(A + (size_t)(rowBase + aRow) * 256 + aHalf * 8 + 4)
              : make_float4(0.f, 0.f, 0.f, 0.f);
    bv0 = *(const float4*)(B + (size_t)(2 * kpB) * 256 + colBase + qB * 4);
    bv1 = *(const float4*)(B + (size_t)(2 * kpB + 1) * 256 + colBase + qB * 4);
    {
        uint32_t h, l;
        int kb = aHalf * 4;
        split2(av0.x, av0.y, h, l); AhB[(kb+0)*PADW + aRow] = h; AlB[(kb+0)*PADW + aRow] = l;
        split2(av0.z, av0.w, h, l); AhB[(kb+1)*PADW + aRow] = h; AlB[(kb+1)*PADW + aRow] = l;
        split2(av1.x, av1.y, h, l); AhB[(kb+2)*PADW + aRow] = h; AlB[(kb+2)*PADW + aRow] = l;
        split2(av1.z, av1.w, h, l); AhB[(kb+3)*PADW + aRow] = h; AlB[(kb+3)*PADW + aRow] = l;
        split2(bv0.x, bv1.x, h, l); BhB[kpB*PADW + qB*4+0] = h; BlB[kpB*PADW + qB*4+0] = l;
        split2(bv0.y, bv1.y, h, l); BhB[kpB*PADW + qB*4+1] = h; BlB[kpB*PADW + qB*4+1] = l;
        split2(bv0.z, bv1.z, h, l); BhB[kpB*PADW + qB*4+2] = h; BlB[kpB*PADW + qB*4+2] = l;
        split2(bv0.w, bv1.w, h, l); BhB[kpB*PADW + qB*4+3] = h; BlB[kpB*PADW + qB*4+3] = l;
    }
    __syncthreads();

    for (int ch = 0; ch < 16; ++ch) {
        const int cur = ch & 1, nxt = cur ^ 1;
        if (ch < 15) {
            const int kg = (ch + 1) * 16;
            av0 = aOk ? *(const float4*)(A + (size_t)(rowBase + aRow) * 256 + kg + aHalf * 8)
                      : make_float4(0.f, 0.f, 0.f, 0.f);
            av1 = aOk ? *(const float4*)(A + (size_t)(rowBase + aRow) * 256 + kg + aHalf * 8 + 4)
                      : make_float4(0.f, 0.f, 0.f, 0.f);
            bv0 = *(const float4*)(B + (size_t)(kg + 2 * kpB) * 256 + colBase + qB * 4);
            bv1 = *(const float4*)(B + (size_t)(kg + 2 * kpB + 1) * 256 + colBase + qB * 4);
        }
        const uint32_t* Ah = AhB + cur * CHU;
        const uint32_t* Al = AlB + cur * CHU;
        const uint32_t* Bh = BhB + cur * CHU;
        const uint32_t* Bl = BlB + cur * CHU;

        uint32_t bhf[4][2], blf[4][2];
        #pragma unroll
        for (int nt = 0; nt < 4; ++nt) {
            int n = warpCol * 32 + nt * 8 + gid;
            bhf[nt][0] = Bh[tig*PADW + n];
            bhf[nt][1] = Bh[(tig+4)*PADW + n];
            blf[nt][0] = Bl[tig*PADW + n];
            blf[nt][1] = Bl[(tig+4)*PADW + n];
        }
        #pragma unroll
        for (int mt = 0; mt < 4; ++mt) {
            int m = warpRow * 64 + mt * 16 + gid;
            uint32_t ahi[4], alo[4];
            ahi[0] = Ah[tig*PADW + m];
            ahi[1] = Ah[tig*PADW + m + 8];
            ahi[2] = Ah[(tig+4)*PADW + m];
            ahi[3] = Ah[(tig+4)*PADW + m + 8];
            alo[0] = Al[tig*PADW + m];
            alo[1] = Al[tig*PADW + m + 8];
            alo[2] = Al[(tig+4)*PADW + m];
            alo[3] = Al[(tig+4)*PADW + m + 8];
            #pragma unroll
            for (int nt = 0; nt < 4; ++nt) {
                MMA_BF16(c[mt][nt], ahi, bhf[nt]);
                MMA_BF16(c[mt][nt], ahi, blf[nt]);
                MMA_BF16(c[mt][nt], alo, bhf[nt]);
            }
        }
        if (ch < 15) {
            uint32_t* Ahn = AhB + nxt * CHU;
            uint32_t* Aln = AlB + nxt * CHU;
            uint32_t* Bhn = BhB + nxt * CHU;
            uint32_t* Bln = BlB + nxt * CHU;
            uint32_t h, l;
            int kb = aHalf * 4;
            split2(av0.x, av0.y, h, l); Ahn[(kb+0)*PADW + aRow] = h; Aln[(kb+0)*PADW + aRow] = l;
            split2(av0.z, av0.w, h, l); Ahn[(kb+1)*PADW + aRow] = h; Aln[(kb+1)*PADW + aRow] = l;
            split2(av1.x, av1.y, h, l); Ahn[(kb+2)*PADW + aRow] = h; Aln[(kb+2)*PADW + aRow] = l;
            split2(av1.z, av1.w, h, l); Ahn[(kb+3)*PADW + aRow] = h; Aln[(kb+3)*PADW + aRow] = l;
            split2(bv0.x, bv1.x, h, l); Bhn[kpB*PADW + qB*4+0] = h; Bln[kpB*PADW + qB*4+0] = l;
            split2(bv0.y, bv1.y, h, l); Bhn[kpB*PADW + qB*4+1] = h; Bln[kpB*PADW + qB*4+1] = l;
            split2(bv0.z, bv1.z, h, l); Bhn[kpB*PADW + qB*4+2] = h; Bln[kpB*PADW + qB*4+2] = l;
            split2(bv0.w, bv1.w, h, l); Bhn[kpB*PADW + qB*4+3] = h; Bln[kpB*PADW + qB*4+3] = l;
            __syncthreads();
        }
    }

    #pragma unroll
    for (int mt = 0; mt < 4; ++mt) {
        int row = rowBase + warpRow * 64 + mt * 16 + gid;
        #pragma unroll
        for (int nt = 0; nt < 4; ++nt) {
            int col = colBase + warpCol * 32 + nt * 8 + tig * 2;
            float b0 = bias ? bias[col] : 0.f;
            float b1 = bias ? bias[col + 1] : 0.f;
            if (row < M) {
                float2 o = make_float2(c[mt][nt][0] + b0, c[mt][nt][1] + b1);
                *(float2*)(C + (size_t)row * 256 + col) = o;
            }
            if (row + 8 < M) {
                float2 o = make_float2(c[mt][nt][2] + b0, c[mt][nt][3] + b1);
                *(float2*)(C + (size_t)(row + 8) * 256 + col) = o;
            }
        }
    }
}

// ---- fused GATv2 edge phase + GraphNorm column stats --------------------
// warp per node, online softmax + aggregate; block-level colsum/colsq.
__global__ __launch_bounds__(256)
void k_gat_fused(const float4* __restrict__ xl, const float4* __restrict__ xr,
                 const float* __restrict__ att) {
    __shared__ float bsum[DD], bsq[DD];
    int tid = threadIdx.x;
    bsum[tid] = 0.f; bsq[tid] = 0.f;
    __syncthreads();

    int node = blockIdx.x * 8 + (tid >> 5);
    int lane = tid & 31;

    float4 xr0 = xr[(size_t)node * 64 + lane * 2];
    float4 xr1 = xr[(size_t)node * 64 + lane * 2 + 1];
    float4 at0 = ((const float4*)att)[lane * 2];
    float4 at1 = ((const float4*)att)[lane * 2 + 1];

    float m = -1e30f, den = 0.f;
    float4 acc0 = make_float4(0.f, 0.f, 0.f, 0.f);
    float4 acc1 = make_float4(0.f, 0.f, 0.f, 0.f);

    int beg = g_off[node], end = g_off[node + 1];
    for (int j = beg; j < end; ++j) {
        int src = g_esrc[j];
        float4 a0 = xl[(size_t)src * 64 + lane * 2];
        float4 a1 = xl[(size_t)src * 64 + lane * 2 + 1];
        float v, p = 0.f;
        v = a0.x + xr0.x; v = v > 0.f ? v : NEG * v; p += at0.x * v;
        v = a0.y + xr0.y; v = v > 0.f ? v : NEG * v; p += at0.y * v;
        v = a0.z + xr0.z; v = v > 0.f ? v : NEG * v; p += at0.z * v;
        v = a0.w + xr0.w; v = v > 0.f ? v : NEG * v; p += at0.w * v;
        v = a1.x + xr1.x; v = v > 0.f ? v : NEG * v; p += at1.x * v;
        v = a1.y + xr1.y; v = v > 0.f ? v : NEG * v; p += at1.y * v;
        v = a1.z + xr1.z; v = v > 0.f ? v : NEG * v; p += at1.z * v;
        v = a1.w + xr1.w; v = v > 0.f ? v : NEG * v; p += at1.w * v;
        p += __shfl_xor_sync(~0u, p, 1);
        p += __shfl_xor_sync(~0u, p, 2);
        p += __shfl_xor_sync(~0u, p, 4);

        if (p <= m) {
            float w = __expf(p - m);
            den += w;
            acc0.x += w * a0.x; acc0.y += w * a0.y;
            acc0.z += w * a0.z; acc0.w += w * a0.w;
            acc1.x += w * a1.x; acc1.y += w * a1.y;
            acc1.z += w * a1.z; acc1.w += w * a1.w;
        } else {
            float sc = __expf(m - p);
            den = den * sc + 1.f;
            acc0.x = acc0.x * sc + a0.x; acc0.y = acc0.y * sc + a0.y;
            acc0.z = acc0.z * sc + a0.z; acc0.w = acc0.w * sc + a0.w;
            acc1.x = acc1.x * sc + a1.x; acc1.y = acc1.y * sc + a1.y;
            acc1.z = acc1.z * sc + a1.z; acc1.w = acc1.w * sc + a1.w;
            m = p;
        }
    }
    float inv = 1.f / (den + SM_EPS);
    acc0.x *= inv; acc0.y *= inv; acc0.z *= inv; acc0.w *= inv;
    acc1.x *= inv; acc1.y *= inv; acc1.z *= inv; acc1.w *= inv;
    ((float4*)g_agg)[(size_t)node * 64 + lane * 2] = acc0;
    ((float4*)g_agg)[(size_t)node * 64 + lane * 2 + 1] = acc1;

    // column stats (raw sums; bconv folded in at finstats)
    int cb = lane * 8;
    atomicAdd(&bsum[cb + 0], acc0.x); atomicAdd(&bsq[cb + 0], acc0.x * acc0.x);
    atomicAdd(&bsum[cb + 1], acc0.y); atomicAdd(&bsq[cb + 1], acc0.y * acc0.y);
    atomicAdd(&bsum[cb + 2], acc0.z); atomicAdd(&bsq[cb + 2], acc0.z * acc0.z);
    atomicAdd(&bsum[cb + 3], acc0.w); atomicAdd(&bsq[cb + 3], acc0.w * acc0.w);
    atomicAdd(&bsum[cb + 4], acc1.x); atomicAdd(&bsq[cb + 4], acc1.x * acc1.x);
    atomicAdd(&bsum[cb + 5], acc1.y); atomicAdd(&bsq[cb + 5], acc1.y * acc1.y);
    atomicAdd(&bsum[cb + 6], acc1.z); atomicAdd(&bsq[cb + 6], acc1.z * acc1.z);
    atomicAdd(&bsum[cb + 7], acc1.w); atomicAdd(&bsq[cb + 7], acc1.w * acc1.w);
    __syncthreads();
    atomicAdd(&g_colstat[tid], bsum[tid]);
    atomicAdd(&g_colstat[DD + tid], bsq[tid]);
}

// ---- fused final-layer GAT: warp per node, lanes = 4 heads x 8 (c<5) ----
__global__ __launch_bounds__(256)
void k_gat_fused_f(const float* __restrict__ fxl, const float* __restrict__ fxr,
                   const float* __restrict__ att) {
    int node = blockIdx.x * 8 + (threadIdx.x >> 5);
    int lane = threadIdx.x & 31;
    int h = lane >> 3, c = lane & 7;
    bool act = c < OUTC;

    float xrv = act ? fxr[(size_t)node * FD + h * OUTC + c] : 0.f;
    float atv = act ? att[h * OUTC + c] : 0.f;

    float m = -1e30f, den = 0.f, acc = 0.f;
    int beg = g_off[node], end = g_off[node + 1];
    for (int j = beg; j < end; ++j) {
        int src = g_esrc[j];
        float a = act ? fxl[(size_t)src * FD + h * OUTC + c] : 0.f;
        float v = a + xrv; v = v > 0.f ? v : NEG * v;
        float p = atv * v;
        p += __shfl_xor_sync(~0u, p, 1);
        p += __shfl_xor_sync(~0u, p, 2);
        p += __shfl_xor_sync(~0u, p, 4);
        if (p <= m) {
            float w = __expf(p - m);
            den += w; acc += w * a;
        } else {
            float sc = __expf(m - p);
            den = den * sc + 1.f; acc = acc * sc + a; m = p;
        }
    }
    if (act)
        g_fagg[(size_t)node * FD + h * OUTC + c] = acc / (den + SM_EPS);
}

// ------- merged final GEMMs: fxl[.,20], fxr[.,20], flin[.,5] in one pass ---
__global__ __launch_bounds__(192)
void k_gemm_f3(const float* __restrict__ A,
               const float* __restrict__ B0, const float* __restrict__ B1,
               const float* __restrict__ B2, const float* __restrict__ bias2,
               float* __restrict__ C0, float* __restrict__ C1,
               float* __restrict__ C2, int M) {
    __shared__ float As[16][129];
    __shared__ float Bs[16][48];
    const int tid = threadIdx.x;
    const int tx = tid % 48, ty = tid / 48;
    const int rowBase = blockIdx.x * 128;

    float acc[32];
    #pragma unroll
    for (int r = 0; r < 32; ++r) acc[r] = 0.f;

    for (int ch = 0; ch < 16; ++ch) {
        for (int i = tid; i < 2048; i += 192) {
            int row = i >> 4, k = i & 15;
            int gr = rowBase + row;
            As[k][row] = (gr < M) ? A[(size_t)gr * 256 + ch * 16 + k] : 0.f;
        }
        for (int i = tid; i < 768; i += 192) {
            int k = i / 48, cc = i % 48;
            float v = 0.f;
            int gk = ch * 16 + k;
            if (cc < FD)            v = B0[(size_t)gk * FD + cc];
            else if (cc < 2 * FD)   v = B1[(size_t)gk * FD + (cc - FD)];
            else if (cc < 2 * FD + OUTC) v = B2[(size_t)gk * OUTC + (cc - 2 * FD)];
            Bs[k][cc] = v;
        }
        __syncthreads();
        #pragma unroll
        for (int k = 0; k < 16; ++k) {
            float b = Bs[k][tx];
            #pragma unroll
            for (int r = 0; r < 32; ++r) acc[r] += As[k][ty * 32 + r] * b;
        }
        __syncthreads();
    }

    #pragma unroll
    for (int r = 0; r < 32; ++r) {
        int row = rowBase + ty * 32 + r;
        if (row >= M) break;
        if (tx < FD) {
            C0[(size_t)row * FD + tx] = acc[r];
        } else if (tx < 2 * FD) {
            C1[(size_t)row * FD + (tx - FD)] = acc[r];
        } else if (tx < 2 * FD + OUTC) {
            C2[(size_t)row * OUTC + (tx - 2 * FD)] = acc[r] + bias2[tx - 2 * FD];
        }
    }
}

// ---------------- CSR build ----------------
__global__ void k_hist(const int* __restrict__ ei) {
    int e = blockIdx.x * blockDim.x + threadIdx.x;
    if (e < EE) atomicAdd(&g_deg[ei[EE + e]], 1);
}

__global__ void k_scan() {
    __shared__ int wsum[32];
    const int CH = 49;
    int t = threadIdx.x;
    int base = t * CH;
    int s = 0;
    for (int i = 0; i < CH; ++i) {
        int idx = base + i;
        if (idx < NN) s += g_deg[idx];
    }
    int lane = t & 31, wid = t >> 5;
    int v = s;
    #pragma unroll
    for (int d = 1; d < 32; d <<= 1) {
        int n = __shfl_up_sync(~0u, v, d);
        if (lane >= d) v += n;
    }
    if (lane == 31) wsum[wid] = v;
    __syncthreads();
    if (wid == 0) {
        int wv = wsum[lane];
        #pragma unroll
        for (int d = 1; d < 32; d <<= 1) {
            int n = __shfl_up_sync(~0u, wv, d);
            if (lane >= d) wv += n;
        }
        wsum[lane] = wv;
    }
    __syncthreads();
    int pre = (v - s) + (wid > 0 ? wsum[wid - 1] : 0);
    for (int i = 0; i < CH; ++i) {
        int idx = base + i;
        if (idx < NN) { g_off[idx] = pre; pre += g_deg[idx]; }
    }
    if (t == 1023) g_off[NN] = pre;
}

__global__ void k_scatter(const int* __restrict__ ei) {
    int e = blockIdx.x * blockDim.x + threadIdx.x;
    if (e >= EE) return;
    int src = ei[e], dst = ei[EE + e];
    int p = atomicAdd(&g_pos[dst], 1);
    g_esrc[g_off[dst] + p] = src;
}

// ---------------- GraphNorm finalize (bconv folded in) ----------------
__global__ void k_finstats(const float* __restrict__ bconv,
                           const float* __restrict__ gnw,
                           const float* __restrict__ gnms) {
    int t = threadIdx.x;
    float bc = bconv[t];
    float mv = g_colstat[t] * (1.f / NN);          // E[v]
    float q  = g_colstat[DD + t] * (1.f / NN);     // E[v^2]
    float mean = mv + bc;                          // E[v+bc]
    float e2 = q + 2.f * bc * mv + bc * bc;        // E[(v+bc)^2]
    float ms = mean * gnms[t];
    float var = e2 - 2.f * ms * mean + ms * ms;
    g_mshift[t] = ms;
    g_rsig[t] = gnw[t] * rsqrtf(var + GN_EPS);
}

__global__ void k_fuse(const float* __restrict__ bconv, const float* __restrict__ gnb) {
    int i = blockIdx.x * blockDim.x + threadIdx.x;
    if (i >= NN * (DD / 4)) return;
    int c4 = (i & 63) * 4;
    float4 v = ((const float4*)g_agg)[i];
    float4 l = ((const float4*)g_lin)[i];
    float4 r;
    float t;
    t = (v.x + bconv[c4+0] - g_mshift[c4+0]) * g_rsig[c4+0] + gnb[c4+0] + l.x;
    r.x = t > 0.f ? t : expm1f(t);
    t = (v.y + bconv[c4+1] - g_mshift[c4+1]) * g_rsig[c4+1] + gnb[c4+1] + l.y;
    r.y = t > 0.f ? t : expm1f(t);
    t = (v.z + bconv[c4+2] - g_mshift[c4+2]) * g_rsig[c4+2] + gnb[c4+2] + l.z;
    r.z = t > 0.f ? t : expm1f(t);
    t = (v.w + bconv[c4+3] - g_mshift[c4+3]) * g_rsig[c4+3] + gnb[c4+3] + l.w;
    r.w = t > 0.f ? t : expm1f(t);
    ((float4*)g_emb)[i] = r;
}

// ---------------- final combine + log_softmax ----------------
__global__ void k_final(const float* __restrict__ fbconv, float* __restrict__ out) {
    int n = blockIdx.x * blockDim.x + threadIdx.x;
    if (n >= NN) return;
    float t[OUTC];
    #pragma unroll
    for (int o = 0; o < OUTC; ++o) {
        float s = 0.f;
        #pragma unroll
        for (int h = 0; h < HH; ++h) s += g_fagg[(size_t)n * FD + h * OUTC + o];
        t[o] = 0.25f * s + fbconv[o] + g_flin[(size_t)n * OUTC + o];
    }
    float m = t[0];
    #pragma unroll
    for (int o = 1; o < OUTC; ++o) m = fmaxf(m, t[o]);
    float lse = 0.f;
    #pragma unroll
    for (int o = 0; o < OUTC; ++o) lse += __expf(t[o] - m);
    lse = __logf(lse);
    #pragma unroll
    for (int o = 0; o < OUTC; ++o) out[(size_t)n * OUTC + o] = t[o] - m - lse;
}

// ---------------- host ----------------
extern "C" void kernel_launch(void* const* d_in, const int* in_sizes, int n_in,
                              void* d_out, int out_size) {
    const float* x      = (const float*)d_in[0];
    const int*   ei     = (const int*)d_in[1];
    const float* Wl     = (const float*)d_in[2];
    const float* Wr     = (const float*)d_in[3];
    const float* att    = (const float*)d_in[4];
    const float* bconv  = (const float*)d_in[5];
    const float* Wlin   = (const float*)d_in[6];
    const float* blin   = (const float*)d_in[7];
    const float* gnw    = (const float*)d_in[8];
    const float* gnb    = (const float*)d_in[9];
    const float* gnms   = (const float*)d_in[10];
    const float* fWl    = (const float*)d_in[11];
    const float* fWr    = (const float*)d_in[12];
    const float* fatt   = (const float*)d_in[13];
    const float* fbconv = (const float*)d_in[14];
    const float* fWlin  = (const float*)d_in[15];
    const float* fblin  = (const float*)d_in[16];
    float* out = (float*)d_out;

    cudaFuncSetAttribute(k_mma3, cudaFuncAttributeMaxDynamicSharedMemorySize,
                         MMA_SMEM);

    float *p_emb, *p_xl, *p_xr, *p_lin, *p_fxl, *p_fxr, *p_flin, *p_colstat;
    int *p_deg, *p_pos;
    cudaGetSymbolAddress((void**)&p_emb,  g_emb);
    cudaGetSymbolAddress((void**)&p_xl,   g_xl);
    cudaGetSymbolAddress((void**)&p_xr,   g_xr);
    cudaGetSymbolAddress((void**)&p_lin,  g_lin);
    cudaGetSymbolAddress((void**)&p_fxl,  g_fxl);
    cudaGetSymbolAddress((void**)&p_fxr,  g_fxr);
    cudaGetSymbolAddress((void**)&p_flin, g_flin);
    cudaGetSymbolAddress((void**)&p_colstat, g_colstat);
    cudaGetSymbolAddress((void**)&p_deg,  g_deg);
    cudaGetSymbolAddress((void**)&p_pos,  g_pos);

    const int E_BLOCKS = (EE + 255) / 256;

    // ---- CSR build ----
    cudaMemsetAsync(p_deg, 0, NN * sizeof(int));
    cudaMemsetAsync(p_pos, 0, NN * sizeof(int));
    k_hist<<<E_BLOCKS, 256>>>(ei);
    k_scan<<<1, 1024>>>();
    k_scatter<<<E_BLOCKS, 256>>>(ei);

    const float* embp = x;
    for (int i = 0; i < 2; ++i) {
        const size_t wo = (size_t)i * DD * DD;
        dim3 grid(6, (NN + 127) / 128);
        k_mma3<<<grid, 256, MMA_SMEM>>>(embp, Wl + wo, Wr + wo, Wlin + wo,
                                        blin + i * DD, p_xl, p_xr, p_lin, NN);
        cudaMemsetAsync(p_colstat, 0, 2 * DD * sizeof(float));
        k_gat_fused<<<NN / 8, 256>>>((const float4*)p_xl, (const float4*)p_xr,
                                     att + i * HH * CC);
        k_finstats<<<1, 256>>>(bconv + i * DD, gnw + i * DD, gnms + i * DD);
        k_fuse<<<(NN * (DD / 4) + 255) / 256, 256>>>(bconv + i * DD, gnb + i * DD);
        embp = p_emb;
    }

    // final layer
    k_gemm_f3<<<(NN + 127) / 128, 192>>>(p_emb, fWl, fWr, fWlin, fblin,
                                         p_fxl, p_fxr, p_flin, NN);
    k_gat_fused_f<<<NN / 8, 256>>>(p_fxl, p_fxr, fatt);
    k_final<<<(NN + 255) / 256, 256>>>(fbconv, out);
}